// round 4
// baseline (speedup 1.0000x reference)
#include <cuda_runtime.h>
#include <math.h>

// Problem constants
#define IN_DIM 44
#define H      128
#define H4     512
#define NL     4
#define TDEC   50
#define BATCH  2048
#define SEQ    200

#define TB  8    // batch tile per block (encoder recurrent)
#define DTB 8    // batch tile per block (decoder)
#define HP  12   // padded batch stride (48B rows -> 16B aligned float4 views)

typedef unsigned long long ull;

// ---------------------------------------------------------------------------
// Device scratch
// ---------------------------------------------------------------------------
__device__ float g_Xg[(long)SEQ * BATCH * H4];
__device__ float g_ys[(long)SEQ * BATCH * H];
__device__ float g_h[NL * BATCH * H];
__device__ float g_c[NL * BATCH * H];
// plain transposed weights WT[k][g]
__device__ float g_encWih0T[IN_DIM * H4];
__device__ float g_encWihRT[3 * H * H4];
__device__ float g_decWih0T[IN_DIM * H4];
__device__ float g_fcT[H * IN_DIM];
// 4-packed recurrent weights: float4 at [(k/2)*256 + t] =
//   { W[2t][k], W[2t+1][k], W[2t][k+1], W[2t+1][k+1] }
__device__ float g_encWhhP[NL * H * H4];
__device__ float g_decWhhP[NL * H * H4];
__device__ float g_decWihRP[3 * H * H4];

// ---------------------------------------------------------------------------
// packed f32x2 helpers
// ---------------------------------------------------------------------------
__device__ __forceinline__ ull pack2(float a, float b) {
    ull r; asm("mov.b64 %0, {%1,%2};" : "=l"(r) : "f"(a), "f"(b)); return r;
}
__device__ __forceinline__ void unpack2(ull v, float& a, float& b) {
    asm("mov.b64 {%0,%1}, %2;" : "=f"(a), "=f"(b) : "l"(v));
}
__device__ __forceinline__ void ffma2(ull& d, ull a, ull b) {
    asm("fma.rn.f32x2 %0, %1, %2, %0;" : "+l"(d) : "l"(a), "l"(b));
}

// ---------------------------------------------------------------------------
// Activations via MUFU.TANH (single-MUFU, ~5e-4 rel err, squashed by gates)
// ---------------------------------------------------------------------------
__device__ __forceinline__ float tanha(float x) {
    float y; asm("tanh.approx.f32 %0, %1;" : "=f"(y) : "f"(x)); return y;
}
__device__ __forceinline__ float sigf(float x) {
    return 0.5f * tanha(0.5f * x) + 0.5f;
}

// ---------------------------------------------------------------------------
// Multi-job plain transpose: src [R][C] -> dst[c*R + r]
// ---------------------------------------------------------------------------
struct TJob { const float* s; float* d; int R; int C; };
struct TJobs { TJob j[6]; int n; };

__global__ void k_trans_multi(TJobs jobs) {
    int job = blockIdx.y;
    if (job >= jobs.n) return;
    TJob J = jobs.j[job];
    int tot = J.R * J.C;
    for (int i = blockIdx.x * blockDim.x + threadIdx.x; i < tot;
         i += gridDim.x * blockDim.x) {
        int r = i / J.C, c = i % J.C;
        J.d[c * J.R + r] = J.s[i];
    }
}

// ---------------------------------------------------------------------------
// 4-pack recurrent weights (src [512][128] row-major)
// ---------------------------------------------------------------------------
struct PJob { const float* s; float* d; };
struct PJobs { PJob j[11]; int n; };

__global__ void k_pack4(PJobs jobs) {
    int job = blockIdx.y;
    if (job >= jobs.n) return;
    const float* src = jobs.j[job].s;
    float4* dst = (float4*)jobs.j[job].d;
    int i = blockIdx.x * blockDim.x + threadIdx.x;   // [0, 16384)
    if (i < (H / 2) * 256) {
        int t = i & 255, k2 = i >> 8;
        int k = 2 * k2;
        float4 v;
        v.x = src[(2 * t) * H + k];
        v.y = src[(2 * t + 1) * H + k];
        v.z = src[(2 * t) * H + k + 1];
        v.w = src[(2 * t + 1) * H + k + 1];
        dst[i] = v;
    }
}

// ---------------------------------------------------------------------------
// Input GEMM: out[r][n] = bias[n] + sum_k A(r,k)*WT[k][n]
// Tile M=64 x N=128, BK=16; thread = 4 rows x 8 cols; dup-A smem.
// ---------------------------------------------------------------------------
template <int KDIM, bool GATHER>
__global__ void __launch_bounds__(256) k_ingemm(const float* __restrict__ A,
                                                const float* __restrict__ WT,
                                                const float* __restrict__ bias,
                                                float* __restrict__ out) {
    __shared__ ull   As[16][64];    // duplicated (a,a)
    __shared__ float Bs[16][128];
    const int m0 = blockIdx.x * 64;
    const int n0 = blockIdx.y * 128;
    const int tid = threadIdx.x;
    const int tx = tid & 15;        // col group: n0 + tx*8
    const int ty = tid >> 4;        // row group: m0 + ty*4 + r

    ull acc[4][4];
    ull z = pack2(0.f, 0.f);
#pragma unroll
    for (int r = 0; r < 4; ++r)
#pragma unroll
        for (int c = 0; c < 4; ++c) acc[r][c] = z;

    const int KT = (KDIM + 15) / 16;
    for (int kb = 0; kb < KT; ++kb) {
        const int k0 = kb * 16;
#pragma unroll
        for (int i = 0; i < 4; ++i) {      // A tile: 1024 elems
            int idx = tid + i * 256;
            int ka = idx & 15, ma = idx >> 4;
            float va = 0.f;
            if (k0 + ka < KDIM) {
                long off;
                if (GATHER) {
                    int row = m0 + ma;
                    int t = row >> 11;
                    int b = row & 2047;
                    off = ((long)b * SEQ + t) * KDIM + (k0 + ka);
                } else {
                    off = (long)(m0 + ma) * KDIM + (k0 + ka);
                }
                va = A[off];
            }
            As[ka][ma] = pack2(va, va);
        }
#pragma unroll
        for (int i = 0; i < 8; ++i) {      // B tile: 2048 elems
            int idx = tid + i * 256;
            int nb = idx & 127, kbb = idx >> 7;
            Bs[kbb][nb] = (k0 + kbb < KDIM) ? WT[(long)(k0 + kbb) * H4 + n0 + nb] : 0.f;
        }
        __syncthreads();
#pragma unroll
        for (int k = 0; k < 16; ++k) {
            ulonglong2 bA = *(const ulonglong2*)&Bs[k][tx * 8];
            ulonglong2 bB = *(const ulonglong2*)&Bs[k][tx * 8 + 4];
#pragma unroll
            for (int r = 0; r < 4; ++r) {
                ull a = As[k][ty * 4 + r];
                ffma2(acc[r][0], a, bA.x);
                ffma2(acc[r][1], a, bA.y);
                ffma2(acc[r][2], a, bB.x);
                ffma2(acc[r][3], a, bB.y);
            }
        }
        __syncthreads();
    }
    float4 bl = *(const float4*)&bias[n0 + tx * 8];
    float4 bh = *(const float4*)&bias[n0 + tx * 8 + 4];
#pragma unroll
    for (int r = 0; r < 4; ++r) {
        float c0, c1, c2, c3, c4, c5, c6, c7;
        unpack2(acc[r][0], c0, c1);
        unpack2(acc[r][1], c2, c3);
        unpack2(acc[r][2], c4, c5);
        unpack2(acc[r][3], c6, c7);
        long orow = m0 + ty * 4 + r;
        float4 v0 = { c0 + bl.x, c1 + bl.y, c2 + bl.z, c3 + bl.w };
        float4 v1 = { c4 + bh.x, c5 + bh.y, c6 + bh.z, c7 + bh.w };
        *(float4*)&out[orow * H4 + n0 + tx * 8]     = v0;
        *(float4*)&out[orow * H4 + n0 + tx * 8 + 4] = v1;
    }
}

// ---------------------------------------------------------------------------
// Encoder recurrent sweep, TB=8. Thread owns gate cols (2t,2t+1) x 8 batch.
// Packed-4 weights (1 LDG.128 per 2 k), h via LDS.128.
// ---------------------------------------------------------------------------
__global__ void __launch_bounds__(256) k_lstm_seq(const float* __restrict__ Wp,
                                                  float* __restrict__ ys,
                                                  float* __restrict__ hfin,
                                                  float* __restrict__ cfin) {
    __shared__ float h_s[H][HP];
    __shared__ float gates_s[TB][H4];
    const int tid = threadIdx.x;
    const int b0 = blockIdx.x * TB;
    const int col = tid & 127, half = tid >> 7;

    for (int i = tid; i < H * HP; i += 256) ((float*)h_s)[i] = 0.f;
    float c_reg[4] = {0.f, 0.f, 0.f, 0.f};
    __syncthreads();

    const float4* wp = (const float4*)Wp + tid;
    for (int t = 0; t < SEQ; ++t) {
        // prefetch Xg rows for this step (hides DRAM latency under k loop)
        const float* xgb = g_Xg + ((long)t * BATCH + b0) * H4 + 2 * tid;
        float2 xr[8];
#pragma unroll
        for (int b = 0; b < 8; ++b) xr[b] = *(const float2*)(xgb + (long)b * H4);

        ull acc[2][4];
        ull z = pack2(0.f, 0.f);
#pragma unroll
        for (int p = 0; p < 4; ++p) { acc[0][p] = z; acc[1][p] = z; }

#pragma unroll 8
        for (int k2 = 0; k2 < H / 2; ++k2) {
            float4 w = wp[k2 * 256];
            const int k = 2 * k2;
            ull w0e = pack2(w.x, w.x), w1e = pack2(w.y, w.y);
            ulonglong2 hA = *(const ulonglong2*)&h_s[k][0];
            ulonglong2 hB = *(const ulonglong2*)&h_s[k][4];
            ffma2(acc[0][0], w0e, hA.x); ffma2(acc[0][1], w0e, hA.y);
            ffma2(acc[0][2], w0e, hB.x); ffma2(acc[0][3], w0e, hB.y);
            ffma2(acc[1][0], w1e, hA.x); ffma2(acc[1][1], w1e, hA.y);
            ffma2(acc[1][2], w1e, hB.x); ffma2(acc[1][3], w1e, hB.y);
            ull w0o = pack2(w.z, w.z), w1o = pack2(w.w, w.w);
            ulonglong2 hC = *(const ulonglong2*)&h_s[k + 1][0];
            ulonglong2 hD = *(const ulonglong2*)&h_s[k + 1][4];
            ffma2(acc[0][0], w0o, hC.x); ffma2(acc[0][1], w0o, hC.y);
            ffma2(acc[0][2], w0o, hD.x); ffma2(acc[0][3], w0o, hD.y);
            ffma2(acc[1][0], w1o, hC.x); ffma2(acc[1][1], w1o, hC.y);
            ffma2(acc[1][2], w1o, hD.x); ffma2(acc[1][3], w1o, hD.y);
        }
#pragma unroll
        for (int p = 0; p < 4; ++p) {
            float g0lo, g0hi, g1lo, g1hi;
            unpack2(acc[0][p], g0lo, g0hi);
            unpack2(acc[1][p], g1lo, g1hi);
            float2 vlo = { g0lo + xr[2 * p].x,     g1lo + xr[2 * p].y };
            float2 vhi = { g0hi + xr[2 * p + 1].x, g1hi + xr[2 * p + 1].y };
            *(float2*)&gates_s[2 * p][2 * tid]     = vlo;
            *(float2*)&gates_s[2 * p + 1][2 * tid] = vhi;
        }
        __syncthreads();
#pragma unroll
        for (int r = 0; r < 4; ++r) {
            int b = 2 * r + half;
            float gi = gates_s[b][col];
            float gf = gates_s[b][col + 128];
            float gg = gates_s[b][col + 256];
            float go = gates_s[b][col + 384];
            float cn = sigf(gf) * c_reg[r] + sigf(gi) * tanha(gg);
            c_reg[r] = cn;
            float hn = sigf(go) * tanha(cn);
            h_s[col][b] = hn;
            ys[((long)t * BATCH + b0 + b) * H + col] = hn;
        }
        __syncthreads();
    }
#pragma unroll
    for (int r = 0; r < 4; ++r) {
        int b = 2 * r + half;
        hfin[(b0 + b) * H + col] = h_s[col][b];
        cfin[(b0 + b) * H + col] = c_reg[r];
    }
}

// ---------------------------------------------------------------------------
// Fused decoder, DTB=8, 256 blocks.
// ---------------------------------------------------------------------------
__global__ void __launch_bounds__(256) k_decoder(const float* __restrict__ x,
                                                 const float* __restrict__ dec_b,
                                                 const float* __restrict__ fc_b,
                                                 float* __restrict__ out) {
    __shared__ float h_s[NL * H * HP];   // (l*H + k)*HP + b
    __shared__ float gates_s[DTB][H4];
    __shared__ float din_s[IN_DIM * HP]; // k*HP + b

    const int tid = threadIdx.x;
    const int b0 = blockIdx.x * DTB;
    const int col = tid & 127, half = tid >> 7;

    for (int i = tid; i < NL * H * DTB; i += 256) {
        int l = i / (H * DTB);
        int rem = i % (H * DTB);
        int k = rem / DTB, b = rem % DTB;
        h_s[(l * H + k) * HP + b] = g_h[((long)l * BATCH + b0 + b) * H + k];
    }
    float c_reg[NL * 4];
#pragma unroll
    for (int l = 0; l < NL; ++l)
#pragma unroll
        for (int r = 0; r < 4; ++r) {
            int b = 2 * r + half;
            c_reg[l * 4 + r] = g_c[((long)l * BATCH + b0 + b) * H + col];
        }
    for (int i = tid; i < IN_DIM * DTB; i += 256) {
        int j = i / DTB, b = i % DTB;
        din_s[j * HP + b] = x[((long)(b0 + b) * SEQ + (SEQ - 1)) * IN_DIM + j];
    }
    __syncthreads();

    for (int t = 0; t < TDEC; ++t) {
#pragma unroll 1
        for (int l = 0; l < NL; ++l) {
            ull acc[2][4];
            ull z = pack2(0.f, 0.f);
#pragma unroll
            for (int p = 0; p < 4; ++p) { acc[0][p] = z; acc[1][p] = z; }

            // recurrent part (packed-4 weights)
            const float4* wr = (const float4*)(g_decWhhP + (long)l * H * H4) + tid;
            const float* hl = h_s + l * H * HP;
#pragma unroll 8
            for (int k2 = 0; k2 < H / 2; ++k2) {
                float4 w = wr[k2 * 256];
                const int k = 2 * k2;
                ull w0e = pack2(w.x, w.x), w1e = pack2(w.y, w.y);
                ulonglong2 hA = *(const ulonglong2*)&hl[k * HP];
                ulonglong2 hB = *(const ulonglong2*)&hl[k * HP + 4];
                ffma2(acc[0][0], w0e, hA.x); ffma2(acc[0][1], w0e, hA.y);
                ffma2(acc[0][2], w0e, hB.x); ffma2(acc[0][3], w0e, hB.y);
                ffma2(acc[1][0], w1e, hA.x); ffma2(acc[1][1], w1e, hA.y);
                ffma2(acc[1][2], w1e, hB.x); ffma2(acc[1][3], w1e, hB.y);
                ull w0o = pack2(w.z, w.z), w1o = pack2(w.w, w.w);
                ulonglong2 hC = *(const ulonglong2*)&hl[(k + 1) * HP];
                ulonglong2 hD = *(const ulonglong2*)&hl[(k + 1) * HP + 4];
                ffma2(acc[0][0], w0o, hC.x); ffma2(acc[0][1], w0o, hC.y);
                ffma2(acc[0][2], w0o, hD.x); ffma2(acc[0][3], w0o, hD.y);
                ffma2(acc[1][0], w1o, hC.x); ffma2(acc[1][1], w1o, hC.y);
                ffma2(acc[1][2], w1o, hD.x); ffma2(acc[1][3], w1o, hD.y);
            }
            // input part
            if (l == 0) {
                const float* wi = g_decWih0T + 2 * tid;
#pragma unroll 4
                for (int k = 0; k < IN_DIM; ++k) {
                    float2 w = *(const float2*)(wi + (long)k * H4);
                    ull wwA = pack2(w.x, w.x), wwB = pack2(w.y, w.y);
                    ulonglong2 dA = *(const ulonglong2*)&din_s[k * HP];
                    ulonglong2 dB = *(const ulonglong2*)&din_s[k * HP + 4];
                    ffma2(acc[0][0], wwA, dA.x); ffma2(acc[0][1], wwA, dA.y);
                    ffma2(acc[0][2], wwA, dB.x); ffma2(acc[0][3], wwA, dB.y);
                    ffma2(acc[1][0], wwB, dA.x); ffma2(acc[1][1], wwB, dA.y);
                    ffma2(acc[1][2], wwB, dB.x); ffma2(acc[1][3], wwB, dB.y);
                }
            } else {
                const float4* wi = (const float4*)(g_decWihRP + (long)(l - 1) * H * H4) + tid;
                const float* hp = h_s + (l - 1) * H * HP;
#pragma unroll 8
                for (int k2 = 0; k2 < H / 2; ++k2) {
                    float4 w = wi[k2 * 256];
                    const int k = 2 * k2;
                    ull w0e = pack2(w.x, w.x), w1e = pack2(w.y, w.y);
                    ulonglong2 hA = *(const ulonglong2*)&hp[k * HP];
                    ulonglong2 hB = *(const ulonglong2*)&hp[k * HP + 4];
                    ffma2(acc[0][0], w0e, hA.x); ffma2(acc[0][1], w0e, hA.y);
                    ffma2(acc[0][2], w0e, hB.x); ffma2(acc[0][3], w0e, hB.y);
                    ffma2(acc[1][0], w1e, hA.x); ffma2(acc[1][1], w1e, hA.y);
                    ffma2(acc[1][2], w1e, hB.x); ffma2(acc[1][3], w1e, hB.y);
                    ull w0o = pack2(w.z, w.z), w1o = pack2(w.w, w.w);
                    ulonglong2 hC = *(const ulonglong2*)&hp[(k + 1) * HP];
                    ulonglong2 hD = *(const ulonglong2*)&hp[(k + 1) * HP + 4];
                    ffma2(acc[0][0], w0o, hC.x); ffma2(acc[0][1], w0o, hC.y);
                    ffma2(acc[0][2], w0o, hD.x); ffma2(acc[0][3], w0o, hD.y);
                    ffma2(acc[1][0], w1o, hC.x); ffma2(acc[1][1], w1o, hC.y);
                    ffma2(acc[1][2], w1o, hD.x); ffma2(acc[1][3], w1o, hD.y);
                }
            }
            float2 bb = *(const float2*)&dec_b[(long)l * H4 + 2 * tid];
#pragma unroll
            for (int p = 0; p < 4; ++p) {
                float g0lo, g0hi, g1lo, g1hi;
                unpack2(acc[0][p], g0lo, g0hi);
                unpack2(acc[1][p], g1lo, g1hi);
                float2 vlo = { g0lo + bb.x, g1lo + bb.y };
                float2 vhi = { g0hi + bb.x, g1hi + bb.y };
                *(float2*)&gates_s[2 * p][2 * tid]     = vlo;
                *(float2*)&gates_s[2 * p + 1][2 * tid] = vhi;
            }
            __syncthreads();
#pragma unroll
            for (int r = 0; r < 4; ++r) {
                int b = 2 * r + half;
                float gi = gates_s[b][col];
                float gf = gates_s[b][col + 128];
                float gg = gates_s[b][col + 256];
                float go = gates_s[b][col + 384];
                float cn = sigf(gf) * c_reg[l * 4 + r] + sigf(gi) * tanha(gg);
                c_reg[l * 4 + r] = cn;
                h_s[(l * H + col) * HP + b] = sigf(go) * tanha(cn);
            }
            __syncthreads();
        }
        // fc: out = h3 @ fcT + fc_b ; feeds next step input
        for (int idx = tid; idx < DTB * IN_DIM; idx += 256) {
            int b = idx / IN_DIM, j = idx % IN_DIM;
            float s = fc_b[j];
            const float* h3 = h_s + (NL - 1) * H * HP + b;
#pragma unroll 8
            for (int k = 0; k < H; ++k)
                s += h3[k * HP] * g_fcT[k * IN_DIM + j];
            out[((long)(b0 + b) * TDEC + t) * IN_DIM + j] = s;
            din_s[j * HP + b] = s;
        }
        __syncthreads();
    }
}

// ---------------------------------------------------------------------------
// Host launcher
// ---------------------------------------------------------------------------
extern "C" void kernel_launch(void* const* d_in, const int* in_sizes, int n_in,
                              void* d_out, int out_size) {
    const float* x        = (const float*)d_in[0];
    const float* enc_Wih0 = (const float*)d_in[2];
    const float* enc_WihR = (const float*)d_in[3];
    const float* enc_Whh  = (const float*)d_in[4];
    const float* enc_b    = (const float*)d_in[5];
    const float* dec_Wih0 = (const float*)d_in[6];
    const float* dec_WihR = (const float*)d_in[7];
    const float* dec_Whh  = (const float*)d_in[8];
    const float* dec_b    = (const float*)d_in[9];
    const float* fc_W     = (const float*)d_in[10];
    const float* fc_b     = (const float*)d_in[11];
    float* out = (float*)d_out;

    float *encWih0T, *encWihRT, *decWih0T, *fcT;
    float *encWhhP, *decWhhP, *decWihRP;
    float *Xg, *ys, *hSt, *cSt;
    cudaGetSymbolAddress((void**)&encWih0T, g_encWih0T);
    cudaGetSymbolAddress((void**)&encWihRT, g_encWihRT);
    cudaGetSymbolAddress((void**)&decWih0T, g_decWih0T);
    cudaGetSymbolAddress((void**)&fcT,      g_fcT);
    cudaGetSymbolAddress((void**)&encWhhP,  g_encWhhP);
    cudaGetSymbolAddress((void**)&decWhhP,  g_decWhhP);
    cudaGetSymbolAddress((void**)&decWihRP, g_decWihRP);
    cudaGetSymbolAddress((void**)&Xg,       g_Xg);
    cudaGetSymbolAddress((void**)&ys,       g_ys);
    cudaGetSymbolAddress((void**)&hSt,      g_h);
    cudaGetSymbolAddress((void**)&cSt,      g_c);

    // plain transposes (for GEMM / decoder layer-0 / fc)
    {
        TJobs jt; jt.n = 6;
        jt.j[0] = { enc_Wih0, encWih0T, H4, IN_DIM };
        for (int r = 0; r < 3; ++r)
            jt.j[1 + r] = { enc_WihR + (long)r * H4 * H, encWihRT + (long)r * H * H4, H4, H };
        jt.j[4] = { dec_Wih0, decWih0T, H4, IN_DIM };
        jt.j[5] = { fc_W, fcT, IN_DIM, H };
        dim3 g(64, 6);
        k_trans_multi<<<g, 256>>>(jt);
    }
    // packed-4 recurrent weights
    {
        PJobs jp; jp.n = 11;
        for (int l = 0; l < NL; ++l) jp.j[l]     = { enc_Whh + (long)l * H4 * H, encWhhP + (long)l * H * H4 };
        for (int l = 0; l < NL; ++l) jp.j[4 + l] = { dec_Whh + (long)l * H4 * H, decWhhP + (long)l * H * H4 };
        for (int r = 0; r < 3; ++r)  jp.j[8 + r] = { dec_WihR + (long)r * H4 * H, decWihRP + (long)r * H * H4 };
        dim3 g(64, 11);
        k_pack4<<<g, 256>>>(jp);
    }

    dim3 ggrid(SEQ * BATCH / 64, H4 / 128);

    // encoder layer 0
    k_ingemm<IN_DIM, true><<<ggrid, 256>>>(x, encWih0T, enc_b, Xg);
    k_lstm_seq<<<BATCH / TB, 256>>>(encWhhP, ys, hSt, cSt);
    // encoder layers 1..3
    for (int l = 1; l < NL; ++l) {
        k_ingemm<H, false><<<ggrid, 256>>>(ys, encWihRT + (long)(l - 1) * H * H4,
                                           enc_b + (long)l * H4, Xg);
        k_lstm_seq<<<BATCH / TB, 256>>>(encWhhP + (long)l * H * H4, ys,
                                        hSt + (long)l * BATCH * H, cSt + (long)l * BATCH * H);
    }
    // fused decoder
    k_decoder<<<BATCH / DTB, 256>>>(x, dec_b, fc_b, out);
}

// round 5
// speedup vs baseline: 1.3509x; 1.3509x over previous
#include <cuda_runtime.h>
#include <math.h>

// Problem constants
#define IN_DIM 44
#define H      128
#define H4     512
#define NL     4
#define TDEC   50
#define BATCH  2048
#define SEQ    200

#define TB  16   // batch tile per block (both recurrent kernels)

typedef unsigned long long ull;

// ---------------------------------------------------------------------------
// Device scratch
// ---------------------------------------------------------------------------
__device__ float g_Xg[(long)SEQ * BATCH * H4];   // gate-interleaved: [row][4c+g]
__device__ float g_ys[(long)SEQ * BATCH * H];
__device__ float g_h[NL * BATCH * H];
__device__ float g_c[NL * BATCH * H];
// permuted-transposed GEMM weights: WTp[k][4c+g] = W[g*128+c][k]
__device__ float g_encWih0Tp[IN_DIM * H4];
__device__ float g_encWihRTp[3 * H * H4];
// permuted biases [l][4c+g]
__device__ float g_encBP[NL * H4];
__device__ float g_decBP[NL * H4];
// gate-grouped packed recurrent/input weights: float4[k*128+c] = {Wi,Wf,Wg,Wo}[c][k]
__device__ float g_encWhhP4[NL * H * H * 4];
__device__ float g_decWhhP4[NL * H * H * 4];
__device__ float g_decWihRP4[3 * H * H * 4];
__device__ float g_decWih0P4[IN_DIM * H * 4];
__device__ float g_fcT[H * IN_DIM];

// ---------------------------------------------------------------------------
// packed f32x2 helpers
// ---------------------------------------------------------------------------
__device__ __forceinline__ ull pack2(float a, float b) {
    ull r; asm("mov.b64 %0, {%1,%2};" : "=l"(r) : "f"(a), "f"(b)); return r;
}
__device__ __forceinline__ void unpack2(ull v, float& a, float& b) {
    asm("mov.b64 {%0,%1}, %2;" : "=f"(a), "=f"(b) : "l"(v));
}
__device__ __forceinline__ void ffma2(ull& d, ull a, ull b) {
    asm("fma.rn.f32x2 %0, %1, %2, %0;" : "+l"(d) : "l"(a), "l"(b));
}

// activations via MUFU.TANH
__device__ __forceinline__ float tanha(float x) {
    float y; asm("tanh.approx.f32 %0, %1;" : "=f"(y) : "f"(x)); return y;
}
__device__ __forceinline__ float sigf(float x) {
    return 0.5f * tanha(0.5f * x) + 0.5f;
}

// ---------------------------------------------------------------------------
// Prep kernel 1: permuted biases + fc transpose
// ---------------------------------------------------------------------------
__global__ void k_misc(const float* __restrict__ enc_b, const float* __restrict__ dec_b,
                       const float* __restrict__ fc_W,
                       float* __restrict__ encBP, float* __restrict__ decBP,
                       float* __restrict__ fcT) {
    int i = blockIdx.x * 256 + threadIdx.x;
    if (i < 2048) {
        int l = i >> 9, n = i & 511;
        encBP[i] = enc_b[l * 512 + ((n & 3) * 128 + (n >> 2))];
    } else if (i < 4096) {
        int i2 = i - 2048;
        int l = i2 >> 9, n = i2 & 511;
        decBP[i2] = dec_b[l * 512 + ((n & 3) * 128 + (n >> 2))];
    } else if (i < 4096 + H * IN_DIM) {
        int i2 = i - 4096;
        int k = i2 / IN_DIM, j = i2 - k * IN_DIM;
        fcT[i2] = fc_W[j * H + k];
    }
}

// ---------------------------------------------------------------------------
// Prep kernel 2: permuted transpose for GEMM weights
// dst[k*512 + n] = src[((n&3)*128 + (n>>2))*K + k]
// ---------------------------------------------------------------------------
struct PTJob { const float* s; float* d; int K; };
struct PTJobs { PTJob j[4]; int n; };

__global__ void k_permT(PTJobs jobs) {
    int job = blockIdx.y;
    if (job >= jobs.n) return;
    PTJob J = jobs.j[job];
    int i = blockIdx.x * 256 + threadIdx.x;
    if (i < J.K * 512) {
        int k = i >> 9, n = i & 511;
        J.d[i] = J.s[((n & 3) * 128 + (n >> 2)) * J.K + k];
    }
}

// ---------------------------------------------------------------------------
// Prep kernel 3: gate-grouped 4-pack
// dst float4[k*128+c] = {src[c*K+k], src[(128+c)*K+k], src[(256+c)*K+k], src[(384+c)*K+k]}
// ---------------------------------------------------------------------------
struct GPJob { const float* s; float* d; int K; };
struct GPJobs { GPJob j[12]; int n; };

__global__ void k_pack4g(GPJobs jobs) {
    int job = blockIdx.y;
    if (job >= jobs.n) return;
    GPJob J = jobs.j[job];
    int i = blockIdx.x * 128 + threadIdx.x;
    if (i < J.K * 128) {
        int k = i >> 7, c = i & 127;
        float4 v;
        v.x = J.s[c * J.K + k];
        v.y = J.s[(128 + c) * J.K + k];
        v.z = J.s[(256 + c) * J.K + k];
        v.w = J.s[(384 + c) * J.K + k];
        ((float4*)J.d)[i] = v;
    }
}

// ---------------------------------------------------------------------------
// Input GEMM: out[r][n] = biasP[n] + sum_k A(r,k)*WTp[k][n]
// Tile M=128 x N=128, BK=16; thread = 8 rows x 8 cols.
// ---------------------------------------------------------------------------
template <int KDIM, bool GATHER>
__global__ void __launch_bounds__(256, 2) k_ingemm(const float* __restrict__ A,
                                                   const float* __restrict__ WT,
                                                   const float* __restrict__ bias,
                                                   float* __restrict__ out) {
    __shared__ float As[16][132];
    __shared__ float Bs[16][132];
    const int m0 = blockIdx.x * 128;
    const int n0 = blockIdx.y * 128;
    const int tid = threadIdx.x;
    const int tx = tid & 15;    // cols n0 + tx*8
    const int ty = tid >> 4;    // rows m0 + ty*8

    ull acc[8][4];
    ull z = pack2(0.f, 0.f);
#pragma unroll
    for (int r = 0; r < 8; ++r)
#pragma unroll
        for (int c = 0; c < 4; ++c) acc[r][c] = z;

    const int KT = (KDIM + 15) / 16;
    for (int kb = 0; kb < KT; ++kb) {
        const int k0 = kb * 16;
#pragma unroll
        for (int i = 0; i < 8; ++i) {       // A tile: 2048 elems
            int idx = tid + i * 256;
            int ka = idx & 15, ma = idx >> 4;
            float va = 0.f;
            if (k0 + ka < KDIM) {
                long off;
                if (GATHER) {
                    int row = m0 + ma;
                    int t = row >> 11;
                    int b = row & 2047;
                    off = ((long)b * SEQ + t) * KDIM + (k0 + ka);
                } else {
                    off = (long)(m0 + ma) * KDIM + (k0 + ka);
                }
                va = A[off];
            }
            As[ka][ma] = va;
        }
#pragma unroll
        for (int i = 0; i < 8; ++i) {       // B tile: 2048 elems
            int idx = tid + i * 256;
            int nb = idx & 127, kbb = idx >> 7;
            Bs[kbb][nb] = (k0 + kbb < KDIM) ? WT[(long)(k0 + kbb) * H4 + n0 + nb] : 0.f;
        }
        __syncthreads();
#pragma unroll
        for (int k = 0; k < 16; ++k) {
            float4 a0 = *(const float4*)&As[k][ty * 8];
            float4 a1 = *(const float4*)&As[k][ty * 8 + 4];
            ulonglong2 bAB = *(const ulonglong2*)&Bs[k][tx * 8];
            ulonglong2 bCD = *(const ulonglong2*)&Bs[k][tx * 8 + 4];
            float av[8] = { a0.x, a0.y, a0.z, a0.w, a1.x, a1.y, a1.z, a1.w };
#pragma unroll
            for (int r = 0; r < 8; ++r) {
                ull aa = pack2(av[r], av[r]);
                ffma2(acc[r][0], aa, bAB.x);
                ffma2(acc[r][1], aa, bAB.y);
                ffma2(acc[r][2], aa, bCD.x);
                ffma2(acc[r][3], aa, bCD.y);
            }
        }
        __syncthreads();
    }
    float4 bl = *(const float4*)&bias[n0 + tx * 8];
    float4 bh = *(const float4*)&bias[n0 + tx * 8 + 4];
#pragma unroll
    for (int r = 0; r < 8; ++r) {
        float c0, c1, c2, c3, c4, c5, c6, c7;
        unpack2(acc[r][0], c0, c1);
        unpack2(acc[r][1], c2, c3);
        unpack2(acc[r][2], c4, c5);
        unpack2(acc[r][3], c6, c7);
        long orow = m0 + ty * 8 + r;
        float4 v0 = { c0 + bl.x, c1 + bl.y, c2 + bl.z, c3 + bl.w };
        float4 v1 = { c4 + bh.x, c5 + bh.y, c6 + bh.z, c7 + bh.w };
        *(float4*)&out[orow * H4 + n0 + tx * 8]     = v0;
        *(float4*)&out[orow * H4 + n0 + tx * 8 + 4] = v1;
    }
}

// ---------------------------------------------------------------------------
// Encoder recurrent sweep. Block = 128 cols x 2 batch-halves (256 thr), TB=16.
// Thread owns all 4 gates of col c for 8 batch rows -> register-resident cell,
// double-buffered h_s, ONE barrier per step.
// ---------------------------------------------------------------------------
__global__ void __launch_bounds__(256, 1) k_lstm_seq(const float4* __restrict__ Wp,
                                                     float* __restrict__ ys,
                                                     float* __restrict__ hfin,
                                                     float* __restrict__ cfin) {
    __shared__ float h_s[2][H][TB];
    const int tid = threadIdx.x;
    const int c = tid & 127, bh = tid >> 7;
    const int b0 = blockIdx.x * TB;

    for (int i = tid; i < H * TB; i += 256) (&h_s[1][0][0])[i] = 0.f;
    float c_reg[8] = {0.f, 0.f, 0.f, 0.f, 0.f, 0.f, 0.f, 0.f};
    __syncthreads();

    const float4* wp = Wp + c;
    for (int t = 0; t < SEQ; ++t) {
        const float4* xg = (const float4*)(g_Xg + ((long)t * BATCH + b0) * H4) + c;
        float4 xr[8];
#pragma unroll
        for (int b = 0; b < 8; ++b) xr[b] = xg[(bh * 8 + b) * 128];

        ull acc[4][4];
        ull z = pack2(0.f, 0.f);
#pragma unroll
        for (int g = 0; g < 4; ++g)
#pragma unroll
            for (int p = 0; p < 4; ++p) acc[g][p] = z;

        const float* hp = &h_s[(t + 1) & 1][0][bh * 8];
#pragma unroll 8
        for (int k = 0; k < H; ++k) {
            float4 w = wp[k * 128];
            ulonglong2 hA = *(const ulonglong2*)(hp + k * TB);
            ulonglong2 hB = *(const ulonglong2*)(hp + k * TB + 4);
            ull w0 = pack2(w.x, w.x);
            ffma2(acc[0][0], w0, hA.x); ffma2(acc[0][1], w0, hA.y);
            ffma2(acc[0][2], w0, hB.x); ffma2(acc[0][3], w0, hB.y);
            ull w1 = pack2(w.y, w.y);
            ffma2(acc[1][0], w1, hA.x); ffma2(acc[1][1], w1, hA.y);
            ffma2(acc[1][2], w1, hB.x); ffma2(acc[1][3], w1, hB.y);
            ull w2 = pack2(w.z, w.z);
            ffma2(acc[2][0], w2, hA.x); ffma2(acc[2][1], w2, hA.y);
            ffma2(acc[2][2], w2, hB.x); ffma2(acc[2][3], w2, hB.y);
            ull w3 = pack2(w.w, w.w);
            ffma2(acc[3][0], w3, hA.x); ffma2(acc[3][1], w3, hA.y);
            ffma2(acc[3][2], w3, hB.x); ffma2(acc[3][3], w3, hB.y);
        }
        // register-resident cell update
        float hv[8];
#pragma unroll
        for (int p = 0; p < 4; ++p) {
            float i0, i1, f0, f1, g0, g1, o0, o1;
            unpack2(acc[0][p], i0, i1);
            unpack2(acc[1][p], f0, f1);
            unpack2(acc[2][p], g0, g1);
            unpack2(acc[3][p], o0, o1);
            int b = 2 * p;
            {
                float gi = i0 + xr[b].x, gf = f0 + xr[b].y;
                float gg = g0 + xr[b].z, go = o0 + xr[b].w;
                float cn = sigf(gf) * c_reg[b] + sigf(gi) * tanha(gg);
                c_reg[b] = cn;
                hv[b] = sigf(go) * tanha(cn);
            }
            b = 2 * p + 1;
            {
                float gi = i1 + xr[b].x, gf = f1 + xr[b].y;
                float gg = g1 + xr[b].z, go = o1 + xr[b].w;
                float cn = sigf(gf) * c_reg[b] + sigf(gi) * tanha(gg);
                c_reg[b] = cn;
                hv[b] = sigf(go) * tanha(cn);
            }
        }
        float* hw = &h_s[t & 1][c][bh * 8];
        *(float4*)hw       = make_float4(hv[0], hv[1], hv[2], hv[3]);
        *(float4*)(hw + 4) = make_float4(hv[4], hv[5], hv[6], hv[7]);
        float* yp = ys + ((long)t * BATCH + b0 + bh * 8) * H + c;
#pragma unroll
        for (int b = 0; b < 8; ++b) yp[(long)b * H] = hv[b];
        __syncthreads();
    }
#pragma unroll
    for (int b = 0; b < 8; ++b) {
        hfin[(b0 + bh * 8 + b) * H + c] = h_s[1][c][bh * 8 + b];
        cfin[(b0 + bh * 8 + b) * H + c] = c_reg[b];
    }
}

// ---------------------------------------------------------------------------
// Fused decoder: same gate-grouped structure; DTB=16, 128 blocks, dynamic smem.
// ---------------------------------------------------------------------------
#define DSM_H   (NL * 2 * H * TB)      // 16384 floats
#define DSM_FCW (H * IN_DIM)           // 5632
#define DSM_DIN (IN_DIM * TB)          // 704
#define DSM_FCB 48
#define DEC_SMEM_BYTES ((DSM_H + DSM_FCW + DSM_DIN + DSM_FCB) * 4)

__global__ void __launch_bounds__(256, 1) k_decoder(const float* __restrict__ x,
                                                    const float* __restrict__ fc_b,
                                                    float* __restrict__ out) {
    extern __shared__ float sm[];
    float* h_s = sm;                      // [(l*2+p)*128 + k]*16 + b
    float* fcw = sm + DSM_H;              // [k*44 + j]
    float* din = fcw + DSM_FCW;           // [k*16 + b]
    float* fcb = din + DSM_DIN;

    const int tid = threadIdx.x;
    const int c = tid & 127, bh = tid >> 7;
    const int b0 = blockIdx.x * TB;

    for (int i = tid; i < NL * H * TB; i += 256) {
        int l = i / (H * TB);
        int r = i - l * (H * TB);
        int k = r / TB, b = r - k * TB;
        h_s[((l * 2 + 1) * H + k) * TB + b] = g_h[((long)l * BATCH + b0 + b) * H + k];
    }
    float c_reg[NL * 8];
#pragma unroll
    for (int l = 0; l < NL; ++l)
#pragma unroll
        for (int b = 0; b < 8; ++b)
            c_reg[l * 8 + b] = g_c[((long)l * BATCH + b0 + bh * 8 + b) * H + c];
    for (int i = tid; i < DSM_FCW; i += 256) fcw[i] = g_fcT[i];
    for (int i = tid; i < IN_DIM * TB; i += 256) {
        int k = i >> 4, b = i & 15;
        din[i] = x[((long)(b0 + b) * SEQ + (SEQ - 1)) * IN_DIM + k];
    }
    for (int i = tid; i < IN_DIM; i += 256) fcb[i] = fc_b[i];
    __syncthreads();

    float4 bias[NL];
#pragma unroll
    for (int l = 0; l < NL; ++l)
        bias[l] = *(const float4*)&g_decBP[l * H4 + 4 * c];

    for (int t = 0; t < TDEC; ++t) {
        const int cur = t & 1, prv = cur ^ 1;
#pragma unroll 1
        for (int l = 0; l < NL; ++l) {
            ull acc[4][4];
            ull z = pack2(0.f, 0.f);
#pragma unroll
            for (int g = 0; g < 4; ++g)
#pragma unroll
                for (int p = 0; p < 4; ++p) acc[g][p] = z;

            // recurrent part
            {
                const float4* wr = (const float4*)g_decWhhP4 + (long)l * H * H + c;
                const float* hp = &h_s[(l * 2 + prv) * H * TB + bh * 8];
#pragma unroll 8
                for (int k = 0; k < H; ++k) {
                    float4 w = wr[k * 128];
                    ulonglong2 hA = *(const ulonglong2*)(hp + k * TB);
                    ulonglong2 hB = *(const ulonglong2*)(hp + k * TB + 4);
                    ull w0 = pack2(w.x, w.x);
                    ffma2(acc[0][0], w0, hA.x); ffma2(acc[0][1], w0, hA.y);
                    ffma2(acc[0][2], w0, hB.x); ffma2(acc[0][3], w0, hB.y);
                    ull w1 = pack2(w.y, w.y);
                    ffma2(acc[1][0], w1, hA.x); ffma2(acc[1][1], w1, hA.y);
                    ffma2(acc[1][2], w1, hB.x); ffma2(acc[1][3], w1, hB.y);
                    ull w2 = pack2(w.z, w.z);
                    ffma2(acc[2][0], w2, hA.x); ffma2(acc[2][1], w2, hA.y);
                    ffma2(acc[2][2], w2, hB.x); ffma2(acc[2][3], w2, hB.y);
                    ull w3 = pack2(w.w, w.w);
                    ffma2(acc[3][0], w3, hA.x); ffma2(acc[3][1], w3, hA.y);
                    ffma2(acc[3][2], w3, hB.x); ffma2(acc[3][3], w3, hB.y);
                }
            }
            // input part
            if (l == 0) {
                const float4* wi = (const float4*)g_decWih0P4 + c;
                const float* dp = din + bh * 8;
#pragma unroll 4
                for (int k = 0; k < IN_DIM; ++k) {
                    float4 w = wi[k * 128];
                    ulonglong2 dA = *(const ulonglong2*)(dp + k * TB);
                    ulonglong2 dB = *(const ulonglong2*)(dp + k * TB + 4);
                    ull w0 = pack2(w.x, w.x);
                    ffma2(acc[0][0], w0, dA.x); ffma2(acc[0][1], w0, dA.y);
                    ffma2(acc[0][2], w0, dB.x); ffma2(acc[0][3], w0, dB.y);
                    ull w1 = pack2(w.y, w.y);
                    ffma2(acc[1][0], w1, dA.x); ffma2(acc[1][1], w1, dA.y);
                    ffma2(acc[1][2], w1, dB.x); ffma2(acc[1][3], w1, dB.y);
                    ull w2 = pack2(w.z, w.z);
                    ffma2(acc[2][0], w2, dA.x); ffma2(acc[2][1], w2, dA.y);
                    ffma2(acc[2][2], w2, dB.x); ffma2(acc[2][3], w2, dB.y);
                    ull w3 = pack2(w.w, w.w);
                    ffma2(acc[3][0], w3, dA.x); ffma2(acc[3][1], w3, dA.y);
                    ffma2(acc[3][2], w3, dB.x); ffma2(acc[3][3], w3, dB.y);
                }
            } else {
                const float4* wi = (const float4*)g_decWihRP4 + (long)(l - 1) * H * H + c;
                const float* hp2 = &h_s[((l - 1) * 2 + cur) * H * TB + bh * 8];
#pragma unroll 8
                for (int k = 0; k < H; ++k) {
                    float4 w = wi[k * 128];
                    ulonglong2 hA = *(const ulonglong2*)(hp2 + k * TB);
                    ulonglong2 hB = *(const ulonglong2*)(hp2 + k * TB + 4);
                    ull w0 = pack2(w.x, w.x);
                    ffma2(acc[0][0], w0, hA.x); ffma2(acc[0][1], w0, hA.y);
                    ffma2(acc[0][2], w0, hB.x); ffma2(acc[0][3], w0, hB.y);
                    ull w1 = pack2(w.y, w.y);
                    ffma2(acc[1][0], w1, hA.x); ffma2(acc[1][1], w1, hA.y);
                    ffma2(acc[1][2], w1, hB.x); ffma2(acc[1][3], w1, hB.y);
                    ull w2 = pack2(w.z, w.z);
                    ffma2(acc[2][0], w2, hA.x); ffma2(acc[2][1], w2, hA.y);
                    ffma2(acc[2][2], w2, hB.x); ffma2(acc[2][3], w2, hB.y);
                    ull w3 = pack2(w.w, w.w);
                    ffma2(acc[3][0], w3, hA.x); ffma2(acc[3][1], w3, hA.y);
                    ffma2(acc[3][2], w3, hB.x); ffma2(acc[3][3], w3, hB.y);
                }
            }
            // register-resident cell
            float4 bb = bias[l];
            float hv[8];
#pragma unroll
            for (int p = 0; p < 4; ++p) {
                float i0, i1, f0, f1, g0, g1, o0, o1;
                unpack2(acc[0][p], i0, i1);
                unpack2(acc[1][p], f0, f1);
                unpack2(acc[2][p], g0, g1);
                unpack2(acc[3][p], o0, o1);
                int b = 2 * p;
                {
                    float gi = i0 + bb.x, gf = f0 + bb.y, gg = g0 + bb.z, go = o0 + bb.w;
                    float cn = sigf(gf) * c_reg[l * 8 + b] + sigf(gi) * tanha(gg);
                    c_reg[l * 8 + b] = cn;
                    hv[b] = sigf(go) * tanha(cn);
                }
                b = 2 * p + 1;
                {
                    float gi = i1 + bb.x, gf = f1 + bb.y, gg = g1 + bb.z, go = o1 + bb.w;
                    float cn = sigf(gf) * c_reg[l * 8 + b] + sigf(gi) * tanha(gg);
                    c_reg[l * 8 + b] = cn;
                    hv[b] = sigf(go) * tanha(cn);
                }
            }
            float* hw = &h_s[((l * 2 + cur) * H + c) * TB + bh * 8];
            *(float4*)hw       = make_float4(hv[0], hv[1], hv[2], hv[3]);
            *(float4*)(hw + 4) = make_float4(hv[4], hv[5], hv[6], hv[7]);
            __syncthreads();
        }
        // fc: out = h3 @ fcT + fc_b ; feeds next step input
        const float* h3 = &h_s[(3 * 2 + cur) * H * TB];
        for (int idx = tid; idx < TB * IN_DIM; idx += 256) {
            int b = idx / IN_DIM, j = idx - b * IN_DIM;
            float s = fcb[j];
#pragma unroll 8
            for (int k = 0; k < H; ++k)
                s += h3[k * TB + b] * fcw[k * IN_DIM + j];
            out[((long)(b0 + b) * TDEC + t) * IN_DIM + j] = s;
            din[j * TB + b] = s;
        }
        __syncthreads();
    }
}

// ---------------------------------------------------------------------------
// Host launcher
// ---------------------------------------------------------------------------
extern "C" void kernel_launch(void* const* d_in, const int* in_sizes, int n_in,
                              void* d_out, int out_size) {
    const float* x        = (const float*)d_in[0];
    const float* enc_Wih0 = (const float*)d_in[2];
    const float* enc_WihR = (const float*)d_in[3];
    const float* enc_Whh  = (const float*)d_in[4];
    const float* enc_b    = (const float*)d_in[5];
    const float* dec_Wih0 = (const float*)d_in[6];
    const float* dec_WihR = (const float*)d_in[7];
    const float* dec_Whh  = (const float*)d_in[8];
    const float* dec_b    = (const float*)d_in[9];
    const float* fc_W     = (const float*)d_in[10];
    const float* fc_b     = (const float*)d_in[11];
    float* out = (float*)d_out;

    float *encWih0Tp, *encWihRTp, *encBP, *decBP;
    float *encWhhP4, *decWhhP4, *decWihRP4, *decWih0P4, *fcT;
    float *Xg, *ys, *hSt, *cSt;
    cudaGetSymbolAddress((void**)&encWih0Tp, g_encWih0Tp);
    cudaGetSymbolAddress((void**)&encWihRTp, g_encWihRTp);
    cudaGetSymbolAddress((void**)&encBP,     g_encBP);
    cudaGetSymbolAddress((void**)&decBP,     g_decBP);
    cudaGetSymbolAddress((void**)&encWhhP4,  g_encWhhP4);
    cudaGetSymbolAddress((void**)&decWhhP4,  g_decWhhP4);
    cudaGetSymbolAddress((void**)&decWihRP4, g_decWihRP4);
    cudaGetSymbolAddress((void**)&decWih0P4, g_decWih0P4);
    cudaGetSymbolAddress((void**)&fcT,       g_fcT);
    cudaGetSymbolAddress((void**)&Xg,        g_Xg);
    cudaGetSymbolAddress((void**)&ys,        g_ys);
    cudaGetSymbolAddress((void**)&hSt,       g_h);
    cudaGetSymbolAddress((void**)&cSt,       g_c);

    cudaFuncSetAttribute(k_decoder, cudaFuncAttributeMaxDynamicSharedMemorySize,
                         DEC_SMEM_BYTES);

    // prep 1: biases + fcT
    k_misc<<<(4096 + H * IN_DIM + 255) / 256, 256>>>(enc_b, dec_b, fc_W,
                                                     encBP, decBP, fcT);
    // prep 2: GEMM weights (permuted transpose)
    {
        PTJobs jp; jp.n = 4;
        jp.j[0] = { enc_Wih0, encWih0Tp, IN_DIM };
        for (int r = 0; r < 3; ++r)
            jp.j[1 + r] = { enc_WihR + (long)r * H4 * H, encWihRTp + (long)r * H * H4, H };
        dim3 g(256, 4);
        k_permT<<<g, 256>>>(jp);
    }
    // prep 3: gate-grouped packs
    {
        GPJobs jg; jg.n = 12;
        for (int l = 0; l < NL; ++l)
            jg.j[l] = { enc_Whh + (long)l * H4 * H, encWhhP4 + (long)l * H * H * 4, H };
        for (int l = 0; l < NL; ++l)
            jg.j[4 + l] = { dec_Whh + (long)l * H4 * H, decWhhP4 + (long)l * H * H * 4, H };
        for (int r = 0; r < 3; ++r)
            jg.j[8 + r] = { dec_WihR + (long)r * H4 * H, decWihRP4 + (long)r * H * H * 4, H };
        jg.j[11] = { dec_Wih0, decWih0P4, IN_DIM };
        dim3 g(128, 12);
        k_pack4g<<<g, 128>>>(jg);
    }

    dim3 ggrid(SEQ * BATCH / 128, H4 / 128);

    // encoder layer 0
    k_ingemm<IN_DIM, true><<<ggrid, 256>>>(x, encWih0Tp, encBP, Xg);
    k_lstm_seq<<<BATCH / TB, 256>>>((const float4*)encWhhP4, ys, hSt, cSt);
    // encoder layers 1..3
    for (int l = 1; l < NL; ++l) {
        k_ingemm<H, false><<<ggrid, 256>>>(ys, encWihRTp + (long)(l - 1) * H * H4,
                                           encBP + (long)l * H4, Xg);
        k_lstm_seq<<<BATCH / TB, 256>>>((const float4*)(encWhhP4 + (long)l * H * H * 4),
                                        ys, hSt + (long)l * BATCH * H,
                                        cSt + (long)l * BATCH * H);
    }
    // fused decoder
    k_decoder<<<BATCH / TB, 256, DEC_SMEM_BYTES>>>(x, fc_b, out);
}

// round 7
// speedup vs baseline: 1.3915x; 1.0300x over previous
#include <cuda_runtime.h>
#include <cstdint>
#include <math.h>

// Problem constants
#define IN_DIM 44
#define H      128
#define H4     512
#define NL     4
#define TDEC   50
#define BATCH  2048
#define SEQ    200

#define TB  16   // batch tile per block (both recurrent kernels)

typedef unsigned long long ull;

// ---------------------------------------------------------------------------
// Device scratch
// ---------------------------------------------------------------------------
__device__ float g_Xg[(long)SEQ * BATCH * H4];   // gate-interleaved: [row][4c+g]
__device__ float g_ys[(long)SEQ * BATCH * H];
__device__ float g_h[NL * BATCH * H];
__device__ float g_c[NL * BATCH * H];
// permuted-transposed GEMM weights: WTp[k][4c+g] = W[g*128+c][k]
__device__ float g_encWih0Tp[IN_DIM * H4];
__device__ float g_encWihRTp[3 * H * H4];
// permuted biases [l][4c+g]
__device__ float g_encBP[NL * H4];
__device__ float g_decBP[NL * H4];
// gate-grouped packed recurrent/input weights: float4[k*128+c] = {Wi,Wf,Wg,Wo}[c][k]
__device__ float g_encWhhP4[NL * H * H * 4];
__device__ float g_decWhhP4[NL * H * H * 4];
__device__ float g_decWihRP4[3 * H * H * 4];
__device__ float g_decWih0P4[IN_DIM * H * 4];
__device__ float g_fcT[H * IN_DIM];

// ---------------------------------------------------------------------------
// packed f32x2 helpers
// ---------------------------------------------------------------------------
__device__ __forceinline__ ull pack2(float a, float b) {
    ull r; asm("mov.b64 %0, {%1,%2};" : "=l"(r) : "f"(a), "f"(b)); return r;
}
__device__ __forceinline__ void unpack2(ull v, float& a, float& b) {
    asm("mov.b64 {%0,%1}, %2;" : "=f"(a), "=f"(b) : "l"(v));
}
__device__ __forceinline__ void ffma2(ull& d, ull a, ull b) {
    asm("fma.rn.f32x2 %0, %1, %2, %0;" : "+l"(d) : "l"(a), "l"(b));
}

// activations via MUFU.TANH
__device__ __forceinline__ float tanha(float x) {
    float y; asm("tanh.approx.f32 %0, %1;" : "=f"(y) : "f"(x)); return y;
}
__device__ __forceinline__ float sigf(float x) {
    return 0.5f * tanha(0.5f * x) + 0.5f;
}

// cp.async helpers
__device__ __forceinline__ void cp16(unsigned int dst, const void* src, int bytes) {
    asm volatile("cp.async.ca.shared.global [%0], [%1], 16, %2;"
                 :: "r"(dst), "l"(src), "r"(bytes));
}
__device__ __forceinline__ void cp_commit() {
    asm volatile("cp.async.commit_group;");
}
__device__ __forceinline__ void cp_wait0() {
    asm volatile("cp.async.wait_group 0;");
}

// ---------------------------------------------------------------------------
// Prep kernel 1: permuted biases + fc transpose
// ---------------------------------------------------------------------------
__global__ void k_misc(const float* __restrict__ enc_b, const float* __restrict__ dec_b,
                       const float* __restrict__ fc_W,
                       float* __restrict__ encBP, float* __restrict__ decBP,
                       float* __restrict__ fcT) {
    int i = blockIdx.x * 256 + threadIdx.x;
    if (i < 2048) {
        int l = i >> 9, n = i & 511;
        encBP[i] = enc_b[l * 512 + ((n & 3) * 128 + (n >> 2))];
    } else if (i < 4096) {
        int i2 = i - 2048;
        int l = i2 >> 9, n = i2 & 511;
        decBP[i2] = dec_b[l * 512 + ((n & 3) * 128 + (n >> 2))];
    } else if (i < 4096 + H * IN_DIM) {
        int i2 = i - 4096;
        int k = i2 / IN_DIM, j = i2 - k * IN_DIM;
        fcT[i2] = fc_W[j * H + k];
    }
}

// ---------------------------------------------------------------------------
// Prep kernel 2: permuted transpose for GEMM weights
// dst[k*512 + n] = src[((n&3)*128 + (n>>2))*K + k]
// ---------------------------------------------------------------------------
struct PTJob { const float* s; float* d; int K; };
struct PTJobs { PTJob j[4]; int n; };

__global__ void k_permT(PTJobs jobs) {
    int job = blockIdx.y;
    if (job >= jobs.n) return;
    PTJob J = jobs.j[job];
    int i = blockIdx.x * 256 + threadIdx.x;
    if (i < J.K * 512) {
        int k = i >> 9, n = i & 511;
        J.d[i] = J.s[((n & 3) * 128 + (n >> 2)) * J.K + k];
    }
}

// ---------------------------------------------------------------------------
// Prep kernel 3: gate-grouped 4-pack
// ---------------------------------------------------------------------------
struct GPJob { const float* s; float* d; int K; };
struct GPJobs { GPJob j[12]; int n; };

__global__ void k_pack4g(GPJobs jobs) {
    int job = blockIdx.y;
    if (job >= jobs.n) return;
    GPJob J = jobs.j[job];
    int i = blockIdx.x * 128 + threadIdx.x;
    if (i < J.K * 128) {
        int k = i >> 7, c = i & 127;
        float4 v;
        v.x = J.s[c * J.K + k];
        v.y = J.s[(128 + c) * J.K + k];
        v.z = J.s[(256 + c) * J.K + k];
        v.w = J.s[(384 + c) * J.K + k];
        ((float4*)J.d)[i] = v;
    }
}

// ---------------------------------------------------------------------------
// Input GEMM with cp.async double buffering.
// out[r][n] = biasP[n] + sum_k A(r,k)*WTp[k][n]
// Tile M=128 x N=128, BK=16; thread = 8 rows x 8 cols.
// ---------------------------------------------------------------------------
template <int KDIM, bool GATHER>
__global__ void __launch_bounds__(256, 2) k_ingemm(const float* __restrict__ A,
                                                   const float* __restrict__ WT,
                                                   const float* __restrict__ bias,
                                                   float* __restrict__ out) {
    __shared__ float As[2][16][132];
    __shared__ float Bs[2][16][128];
    const int m0 = blockIdx.x * 128;
    const int n0 = blockIdx.y * 128;
    const int tid = threadIdx.x;
    const int tx = tid & 15;    // cols n0 + tx*8
    const int ty = tid >> 4;    // rows m0 + ty*8
    const int KT = (KDIM + 15) / 16;

    // staging index decomposition (2 chunks per thread each for A and B)
    const int a_m  = tid >> 2;
    const int a_k4 = tid & 3;
    const int b_nb = tid & 31;
    const int b_kb = tid >> 5;

    ull acc[8][4];
    ull z = pack2(0.f, 0.f);
#pragma unroll
    for (int r = 0; r < 8; ++r)
#pragma unroll
        for (int c = 0; c < 4; ++c) acc[r][c] = z;

    float4 ar[2];

    // ---- staging lambdas ----
    auto stageA = [&](int k0) {
#pragma unroll
        for (int i = 0; i < 2; ++i) {
            int m = a_m + i * 64;
            int k = k0 + a_k4 * 4;
            float4 v = {0.f, 0.f, 0.f, 0.f};
            if (k + 3 < KDIM) {          // KDIM % 4 == 0 for both 44 and 128
                long off;
                if (GATHER) {
                    int row = m0 + m;
                    int t = row >> 11;
                    int b = row & 2047;
                    off = ((long)b * SEQ + t) * KDIM + k;
                } else {
                    off = (long)(m0 + m) * KDIM + k;
                }
                v = *(const float4*)(A + off);
            }
            ar[i] = v;
        }
    };
    auto issueB = [&](int k0, int buf) {
#pragma unroll
        for (int i = 0; i < 2; ++i) {
            int kbb = b_kb + i * 8;
            const float* src = WT + (long)(k0 + kbb) * H4 + n0 + b_nb * 4;
            unsigned int dst =
                (unsigned int)__cvta_generic_to_shared(&Bs[buf][kbb][b_nb * 4]);
            cp16(dst, src, (k0 + kbb < KDIM) ? 16 : 0);
        }
        cp_commit();
    };
    auto storeA = [&](int buf) {
#pragma unroll
        for (int i = 0; i < 2; ++i) {
            int m = a_m + i * 64;
            As[buf][a_k4 * 4 + 0][m] = ar[i].x;
            As[buf][a_k4 * 4 + 1][m] = ar[i].y;
            As[buf][a_k4 * 4 + 2][m] = ar[i].z;
            As[buf][a_k4 * 4 + 3][m] = ar[i].w;
        }
    };

    // ---- prologue: tile 0 ----
    issueB(0, 0);
    stageA(0);
    storeA(0);
    cp_wait0();
    __syncthreads();

    for (int kb = 0; kb < KT; ++kb) {
        const int buf = kb & 1;
        const bool more = (kb + 1 < KT);
        if (more) {
            issueB((kb + 1) * 16, buf ^ 1);
            stageA((kb + 1) * 16);
        }
        // ---- compute tile kb ----
#pragma unroll
        for (int k = 0; k < 16; ++k) {
            float4 a0 = *(const float4*)&As[buf][k][ty * 8];
            float4 a1 = *(const float4*)&As[buf][k][ty * 8 + 4];
            ulonglong2 bAB = *(const ulonglong2*)&Bs[buf][k][tx * 8];
            ulonglong2 bCD = *(const ulonglong2*)&Bs[buf][k][tx * 8 + 4];
            float av[8] = { a0.x, a0.y, a0.z, a0.w, a1.x, a1.y, a1.z, a1.w };
#pragma unroll
            for (int r = 0; r < 8; ++r) {
                ull aa = pack2(av[r], av[r]);
                ffma2(acc[r][0], aa, bAB.x);
                ffma2(acc[r][1], aa, bAB.y);
                ffma2(acc[r][2], aa, bCD.x);
                ffma2(acc[r][3], aa, bCD.y);
            }
        }
        if (more) {
            storeA(buf ^ 1);
            cp_wait0();
            __syncthreads();
        }
    }

    float4 bl = *(const float4*)&bias[n0 + tx * 8];
    float4 bh = *(const float4*)&bias[n0 + tx * 8 + 4];
#pragma unroll
    for (int r = 0; r < 8; ++r) {
        float c0, c1, c2, c3, c4, c5, c6, c7;
        unpack2(acc[r][0], c0, c1);
        unpack2(acc[r][1], c2, c3);
        unpack2(acc[r][2], c4, c5);
        unpack2(acc[r][3], c6, c7);
        long orow = m0 + ty * 8 + r;
        float4 v0 = { c0 + bl.x, c1 + bl.y, c2 + bl.z, c3 + bl.w };
        float4 v1 = { c4 + bh.x, c5 + bh.y, c6 + bh.z, c7 + bh.w };
        *(float4*)&out[orow * H4 + n0 + tx * 8]     = v0;
        *(float4*)&out[orow * H4 + n0 + tx * 8 + 4] = v1;
    }
}

// ---------------------------------------------------------------------------
// Encoder recurrent sweep. Block = 128 cols x 2 batch-halves (256 thr), TB=16.
// Gate-grouped, register-resident cell, double-buffered h_s, 1 barrier/step.
// ---------------------------------------------------------------------------
__global__ void __launch_bounds__(256, 1) k_lstm_seq(const float4* __restrict__ Wp,
                                                     float* __restrict__ ys,
                                                     float* __restrict__ hfin,
                                                     float* __restrict__ cfin) {
    __shared__ float h_s[2][H][TB];
    const int tid = threadIdx.x;
    const int c = tid & 127, bh = tid >> 7;
    const int b0 = blockIdx.x * TB;

    for (int i = tid; i < H * TB; i += 256) (&h_s[1][0][0])[i] = 0.f;
    float c_reg[8] = {0.f, 0.f, 0.f, 0.f, 0.f, 0.f, 0.f, 0.f};
    __syncthreads();

    const float4* wp = Wp + c;
    for (int t = 0; t < SEQ; ++t) {
        const float4* xg = (const float4*)(g_Xg + ((long)t * BATCH + b0) * H4) + c;
        float4 xr[8];
#pragma unroll
        for (int b = 0; b < 8; ++b) xr[b] = xg[(bh * 8 + b) * 128];

        ull acc[4][4];
        ull z = pack2(0.f, 0.f);
#pragma unroll
        for (int g = 0; g < 4; ++g)
#pragma unroll
            for (int p = 0; p < 4; ++p) acc[g][p] = z;

        const float* hp = &h_s[(t + 1) & 1][0][bh * 8];
#pragma unroll 8
        for (int k = 0; k < H; ++k) {
            float4 w = wp[k * 128];
            ulonglong2 hA = *(const ulonglong2*)(hp + k * TB);
            ulonglong2 hB = *(const ulonglong2*)(hp + k * TB + 4);
            ull w0 = pack2(w.x, w.x);
            ffma2(acc[0][0], w0, hA.x); ffma2(acc[0][1], w0, hA.y);
            ffma2(acc[0][2], w0, hB.x); ffma2(acc[0][3], w0, hB.y);
            ull w1 = pack2(w.y, w.y);
            ffma2(acc[1][0], w1, hA.x); ffma2(acc[1][1], w1, hA.y);
            ffma2(acc[1][2], w1, hB.x); ffma2(acc[1][3], w1, hB.y);
            ull w2 = pack2(w.z, w.z);
            ffma2(acc[2][0], w2, hA.x); ffma2(acc[2][1], w2, hA.y);
            ffma2(acc[2][2], w2, hB.x); ffma2(acc[2][3], w2, hB.y);
            ull w3 = pack2(w.w, w.w);
            ffma2(acc[3][0], w3, hA.x); ffma2(acc[3][1], w3, hA.y);
            ffma2(acc[3][2], w3, hB.x); ffma2(acc[3][3], w3, hB.y);
        }
        float hv[8];
#pragma unroll
        for (int p = 0; p < 4; ++p) {
            float i0, i1, f0, f1, g0, g1, o0, o1;
            unpack2(acc[0][p], i0, i1);
            unpack2(acc[1][p], f0, f1);
            unpack2(acc[2][p], g0, g1);
            unpack2(acc[3][p], o0, o1);
            int b = 2 * p;
            {
                float gi = i0 + xr[b].x, gf = f0 + xr[b].y;
                float gg = g0 + xr[b].z, go = o0 + xr[b].w;
                float cn = sigf(gf) * c_reg[b] + sigf(gi) * tanha(gg);
                c_reg[b] = cn;
                hv[b] = sigf(go) * tanha(cn);
            }
            b = 2 * p + 1;
            {
                float gi = i1 + xr[b].x, gf = f1 + xr[b].y;
                float gg = g1 + xr[b].z, go = o1 + xr[b].w;
                float cn = sigf(gf) * c_reg[b] + sigf(gi) * tanha(gg);
                c_reg[b] = cn;
                hv[b] = sigf(go) * tanha(cn);
            }
        }
        float* hw = &h_s[t & 1][c][bh * 8];
        *(float4*)hw       = make_float4(hv[0], hv[1], hv[2], hv[3]);
        *(float4*)(hw + 4) = make_float4(hv[4], hv[5], hv[6], hv[7]);
        float* yp = ys + ((long)t * BATCH + b0 + bh * 8) * H + c;
#pragma unroll
        for (int b = 0; b < 8; ++b) yp[(long)b * H] = hv[b];
        __syncthreads();
    }
#pragma unroll
    for (int b = 0; b < 8; ++b) {
        hfin[(b0 + bh * 8 + b) * H + c] = h_s[1][c][bh * 8 + b];
        cfin[(b0 + bh * 8 + b) * H + c] = c_reg[b];
    }
}

// ---------------------------------------------------------------------------
// Fused decoder: gate-grouped; DTB=16, 128 blocks, dynamic smem.
// ---------------------------------------------------------------------------
#define DSM_H   (NL * 2 * H * TB)      // 16384 floats
#define DSM_FCW (H * IN_DIM)           // 5632
#define DSM_DIN (IN_DIM * TB)          // 704
#define DSM_FCB 48
#define DEC_SMEM_BYTES ((DSM_H + DSM_FCW + DSM_DIN + DSM_FCB) * 4)

__global__ void __launch_bounds__(256, 1) k_decoder(const float* __restrict__ x,
                                                    const float* __restrict__ fc_b,
                                                    float* __restrict__ out) {
    extern __shared__ float sm[];
    float* h_s = sm;                      // [(l*2+p)*128 + k]*16 + b
    float* fcw = sm + DSM_H;              // [k*44 + j]
    float* din = fcw + DSM_FCW;           // [k*16 + b]
    float* fcb = din + DSM_DIN;

    const int tid = threadIdx.x;
    const int c = tid & 127, bh = tid >> 7;
    const int b0 = blockIdx.x * TB;

    for (int i = tid; i < NL * H * TB; i += 256) {
        int l = i / (H * TB);
        int r = i - l * (H * TB);
        int k = r / TB, b = r - k * TB;
        h_s[((l * 2 + 1) * H + k) * TB + b] = g_h[((long)l * BATCH + b0 + b) * H + k];
    }
    float c_reg[NL * 8];
#pragma unroll
    for (int l = 0; l < NL; ++l)
#pragma unroll
        for (int b = 0; b < 8; ++b)
            c_reg[l * 8 + b] = g_c[((long)l * BATCH + b0 + bh * 8 + b) * H + c];
    for (int i = tid; i < DSM_FCW; i += 256) fcw[i] = g_fcT[i];
    for (int i = tid; i < IN_DIM * TB; i += 256) {
        int k = i >> 4, b = i & 15;
        din[i] = x[((long)(b0 + b) * SEQ + (SEQ - 1)) * IN_DIM + k];
    }
    for (int i = tid; i < IN_DIM; i += 256) fcb[i] = fc_b[i];
    __syncthreads();

    float4 bias[NL];
#pragma unroll
    for (int l = 0; l < NL; ++l)
        bias[l] = *(const float4*)&g_decBP[l * H4 + 4 * c];

    for (int t = 0; t < TDEC; ++t) {
        const int cur = t & 1, prv = cur ^ 1;
#pragma unroll 1
        for (int l = 0; l < NL; ++l) {
            ull acc[4][4];
            ull z = pack2(0.f, 0.f);
#pragma unroll
            for (int g = 0; g < 4; ++g)
#pragma unroll
                for (int p = 0; p < 4; ++p) acc[g][p] = z;

            {
                const float4* wr = (const float4*)g_decWhhP4 + (long)l * H * H + c;
                const float* hp = &h_s[(l * 2 + prv) * H * TB + bh * 8];
#pragma unroll 8
                for (int k = 0; k < H; ++k) {
                    float4 w = wr[k * 128];
                    ulonglong2 hA = *(const ulonglong2*)(hp + k * TB);
                    ulonglong2 hB = *(const ulonglong2*)(hp + k * TB + 4);
                    ull w0 = pack2(w.x, w.x);
                    ffma2(acc[0][0], w0, hA.x); ffma2(acc[0][1], w0, hA.y);
                    ffma2(acc[0][2], w0, hB.x); ffma2(acc[0][3], w0, hB.y);
                    ull w1 = pack2(w.y, w.y);
                    ffma2(acc[1][0], w1, hA.x); ffma2(acc[1][1], w1, hA.y);
                    ffma2(acc[1][2], w1, hB.x); ffma2(acc[1][3], w1, hB.y);
                    ull w2 = pack2(w.z, w.z);
                    ffma2(acc[2][0], w2, hA.x); ffma2(acc[2][1], w2, hA.y);
                    ffma2(acc[2][2], w2, hB.x); ffma2(acc[2][3], w2, hB.y);
                    ull w3 = pack2(w.w, w.w);
                    ffma2(acc[3][0], w3, hA.x); ffma2(acc[3][1], w3, hA.y);
                    ffma2(acc[3][2], w3, hB.x); ffma2(acc[3][3], w3, hB.y);
                }
            }
            if (l == 0) {
                const float4* wi = (const float4*)g_decWih0P4 + c;
                const float* dp = din + bh * 8;
#pragma unroll 4
                for (int k = 0; k < IN_DIM; ++k) {
                    float4 w = wi[k * 128];
                    ulonglong2 dA = *(const ulonglong2*)(dp + k * TB);
                    ulonglong2 dB = *(const ulonglong2*)(dp + k * TB + 4);
                    ull w0 = pack2(w.x, w.x);
                    ffma2(acc[0][0], w0, dA.x); ffma2(acc[0][1], w0, dA.y);
                    ffma2(acc[0][2], w0, dB.x); ffma2(acc[0][3], w0, dB.y);
                    ull w1 = pack2(w.y, w.y);
                    ffma2(acc[1][0], w1, dA.x); ffma2(acc[1][1], w1, dA.y);
                    ffma2(acc[1][2], w1, dB.x); ffma2(acc[1][3], w1, dB.y);
                    ull w2 = pack2(w.z, w.z);
                    ffma2(acc[2][0], w2, dA.x); ffma2(acc[2][1], w2, dA.y);
                    ffma2(acc[2][2], w2, dB.x); ffma2(acc[2][3], w2, dB.y);
                    ull w3 = pack2(w.w, w.w);
                    ffma2(acc[3][0], w3, dA.x); ffma2(acc[3][1], w3, dA.y);
                    ffma2(acc[3][2], w3, dB.x); ffma2(acc[3][3], w3, dB.y);
                }
            } else {
                const float4* wi = (const float4*)g_decWihRP4 + (long)(l - 1) * H * H + c;
                const float* hp2 = &h_s[((l - 1) * 2 + cur) * H * TB + bh * 8];
#pragma unroll 8
                for (int k = 0; k < H; ++k) {
                    float4 w = wi[k * 128];
                    ulonglong2 hA = *(const ulonglong2*)(hp2 + k * TB);
                    ulonglong2 hB = *(const ulonglong2*)(hp2 + k * TB + 4);
                    ull w0 = pack2(w.x, w.x);
                    ffma2(acc[0][0], w0, hA.x); ffma2(acc[0][1], w0, hA.y);
                    ffma2(acc[0][2], w0, hB.x); ffma2(acc[0][3], w0, hB.y);
                    ull w1 = pack2(w.y, w.y);
                    ffma2(acc[1][0], w1, hA.x); ffma2(acc[1][1], w1, hA.y);
                    ffma2(acc[1][2], w1, hB.x); ffma2(acc[1][3], w1, hB.y);
                    ull w2 = pack2(w.z, w.z);
                    ffma2(acc[2][0], w2, hA.x); ffma2(acc[2][1], w2, hA.y);
                    ffma2(acc[2][2], w2, hB.x); ffma2(acc[2][3], w2, hB.y);
                    ull w3 = pack2(w.w, w.w);
                    ffma2(acc[3][0], w3, hA.x); ffma2(acc[3][1], w3, hA.y);
                    ffma2(acc[3][2], w3, hB.x); ffma2(acc[3][3], w3, hB.y);
                }
            }
            float4 bb = bias[l];
            float hv[8];
#pragma unroll
            for (int p = 0; p < 4; ++p) {
                float i0, i1, f0, f1, g0, g1, o0, o1;
                unpack2(acc[0][p], i0, i1);
                unpack2(acc[1][p], f0, f1);
                unpack2(acc[2][p], g0, g1);
                unpack2(acc[3][p], o0, o1);
                int b = 2 * p;
                {
                    float gi = i0 + bb.x, gf = f0 + bb.y, gg = g0 + bb.z, go = o0 + bb.w;
                    float cn = sigf(gf) * c_reg[l * 8 + b] + sigf(gi) * tanha(gg);
                    c_reg[l * 8 + b] = cn;
                    hv[b] = sigf(go) * tanha(cn);
                }
                b = 2 * p + 1;
                {
                    float gi = i1 + bb.x, gf = f1 + bb.y, gg = g1 + bb.z, go = o1 + bb.w;
                    float cn = sigf(gf) * c_reg[l * 8 + b] + sigf(gi) * tanha(gg);
                    c_reg[l * 8 + b] = cn;
                    hv[b] = sigf(go) * tanha(cn);
                }
            }
            float* hw = &h_s[((l * 2 + cur) * H + c) * TB + bh * 8];
            *(float4*)hw       = make_float4(hv[0], hv[1], hv[2], hv[3]);
            *(float4*)(hw + 4) = make_float4(hv[4], hv[5], hv[6], hv[7]);
            __syncthreads();
        }
        const float* h3 = &h_s[(3 * 2 + cur) * H * TB];
        for (int idx = tid; idx < TB * IN_DIM; idx += 256) {
            int b = idx / IN_DIM, j = idx - b * IN_DIM;
            float s = fcb[j];
#pragma unroll 8
            for (int k = 0; k < H; ++k)
                s += h3[k * TB + b] * fcw[k * IN_DIM + j];
            out[((long)(b0 + b) * TDEC + t) * IN_DIM + j] = s;
            din[j * TB + b] = s;
        }
        __syncthreads();
    }
}

// ---------------------------------------------------------------------------
// Host launcher
// ---------------------------------------------------------------------------
extern "C" void kernel_launch(void* const* d_in, const int* in_sizes, int n_in,
                              void* d_out, int out_size) {
    const float* x        = (const float*)d_in[0];
    const float* enc_Wih0 = (const float*)d_in[2];
    const float* enc_WihR = (const float*)d_in[3];
    const float* enc_Whh  = (const float*)d_in[4];
    const float* enc_b    = (const float*)d_in[5];
    const float* dec_Wih0 = (const float*)d_in[6];
    const float* dec_WihR = (const float*)d_in[7];
    const float* dec_Whh  = (const float*)d_in[8];
    const float* dec_b    = (const float*)d_in[9];
    const float* fc_W     = (const float*)d_in[10];
    const float* fc_b     = (const float*)d_in[11];
    float* out = (float*)d_out;

    float *encWih0Tp, *encWihRTp, *encBP, *decBP;
    float *encWhhP4, *decWhhP4, *decWihRP4, *decWih0P4, *fcT;
    float *Xg, *ys, *hSt, *cSt;
    cudaGetSymbolAddress((void**)&encWih0Tp, g_encWih0Tp);
    cudaGetSymbolAddress((void**)&encWihRTp, g_encWihRTp);
    cudaGetSymbolAddress((void**)&encBP,     g_encBP);
    cudaGetSymbolAddress((void**)&decBP,     g_decBP);
    cudaGetSymbolAddress((void**)&encWhhP4,  g_encWhhP4);
    cudaGetSymbolAddress((void**)&decWhhP4,  g_decWhhP4);
    cudaGetSymbolAddress((void**)&decWihRP4, g_decWihRP4);
    cudaGetSymbolAddress((void**)&decWih0P4, g_decWih0P4);
    cudaGetSymbolAddress((void**)&fcT,       g_fcT);
    cudaGetSymbolAddress((void**)&Xg,        g_Xg);
    cudaGetSymbolAddress((void**)&ys,        g_ys);
    cudaGetSymbolAddress((void**)&hSt,       g_h);
    cudaGetSymbolAddress((void**)&cSt,       g_c);

    cudaFuncSetAttribute(k_decoder, cudaFuncAttributeMaxDynamicSharedMemorySize,
                         DEC_SMEM_BYTES);

    // prep 1: biases + fcT
    k_misc<<<(4096 + H * IN_DIM + 255) / 256, 256>>>(enc_b, dec_b, fc_W,
                                                     encBP, decBP, fcT);
    // prep 2: GEMM weights (permuted transpose)
    {
        PTJobs jp; jp.n = 4;
        jp.j[0] = { enc_Wih0, encWih0Tp, IN_DIM };
        for (int r = 0; r < 3; ++r)
            jp.j[1 + r] = { enc_WihR + (long)r * H4 * H, encWihRTp + (long)r * H * H4, H };
        dim3 g(256, 4);
        k_permT<<<g, 256>>>(jp);
    }
    // prep 3: gate-grouped packs
    {
        GPJobs jg; jg.n = 12;
        for (int l = 0; l < NL; ++l)
            jg.j[l] = { enc_Whh + (long)l * H4 * H, encWhhP4 + (long)l * H * H * 4, H };
        for (int l = 0; l < NL; ++l)
            jg.j[4 + l] = { dec_Whh + (long)l * H4 * H, decWhhP4 + (long)l * H * H * 4, H };
        for (int r = 0; r < 3; ++r)
            jg.j[8 + r] = { dec_WihR + (long)r * H4 * H, decWihRP4 + (long)r * H * H * 4, H };
        jg.j[11] = { dec_Wih0, decWih0P4, IN_DIM };
        dim3 g(128, 12);
        k_pack4g<<<g, 128>>>(jg);
    }

    dim3 ggrid(SEQ * BATCH / 128, H4 / 128);

    // encoder layer 0
    k_ingemm<IN_DIM, true><<<ggrid, 256>>>(x, encWih0Tp, encBP, Xg);
    k_lstm_seq<<<BATCH / TB, 256>>>((const float4*)encWhhP4, ys, hSt, cSt);
    // encoder layers 1..3
    for (int l = 1; l < NL; ++l) {
        k_ingemm<H, false><<<ggrid, 256>>>(ys, encWihRTp + (long)(l - 1) * H * H4,
                                           encBP + (long)l * H4, Xg);
        k_lstm_seq<<<BATCH / TB, 256>>>((const float4*)(encWhhP4 + (long)l * H * H * 4),
                                        ys, hSt + (long)l * BATCH * H,
                                        cSt + (long)l * BATCH * H);
    }
    // fused decoder
    k_decoder<<<BATCH / TB, 256, DEC_SMEM_BYTES>>>(x, fc_b, out);
}

// round 9
// speedup vs baseline: 1.4382x; 1.0336x over previous
#include <cuda_runtime.h>
#include <cuda_bf16.h>
#include <cstdint>
#include <math.h>

// Problem constants
#define IN_DIM 44
#define H      128
#define H4     512
#define NL     4
#define TDEC   50
#define BATCH  2048
#define SEQ    200

#define TB  16   // batch tile per block (both recurrent kernels)

typedef unsigned long long ull;

// ---------------------------------------------------------------------------
// Device scratch
// ---------------------------------------------------------------------------
__device__ float g_Xg[(long)SEQ * BATCH * H4];   // gate-interleaved: [row][4c+g]
__device__ float g_ys[(long)SEQ * BATCH * H];
__device__ float g_h[NL * BATCH * H];
__device__ float g_c[NL * BATCH * H];
// permuted biases [l][4c+g]
__device__ float g_encBP[NL * H4];
__device__ float g_decBP[NL * H4];
// gate-grouped packed recurrent/input weights: float4[k*128+c] = {Wi,Wf,Wg,Wo}[c][k]
__device__ float g_encWhhP4[NL * H * H * 4];
__device__ float g_decWhhP4[NL * H * H * 4];
__device__ float g_decWihRP4[3 * H * H * 4];
__device__ float g_decWih0P4[IN_DIM * H * 4];
__device__ float g_fcT[H * IN_DIM];
// bf16 hi/lo GEMM weight planes, gate-permuted [n][k] (k padded)
__device__ __nv_bfloat16 g_W0H[512 * 48];
__device__ __nv_bfloat16 g_W0L[512 * 48];
__device__ __nv_bfloat16 g_WRH[3 * 512 * 128];
__device__ __nv_bfloat16 g_WRL[3 * 512 * 128];

// ---------------------------------------------------------------------------
// packed f32x2 helpers
// ---------------------------------------------------------------------------
__device__ __forceinline__ ull pack2(float a, float b) {
    ull r; asm("mov.b64 %0, {%1,%2};" : "=l"(r) : "f"(a), "f"(b)); return r;
}
__device__ __forceinline__ void unpack2(ull v, float& a, float& b) {
    asm("mov.b64 {%0,%1}, %2;" : "=f"(a), "=f"(b) : "l"(v));
}
__device__ __forceinline__ void ffma2(ull& d, ull a, ull b) {
    asm("fma.rn.f32x2 %0, %1, %2, %0;" : "+l"(d) : "l"(a), "l"(b));
}

// activations via MUFU.TANH
__device__ __forceinline__ float tanha(float x) {
    float y; asm("tanh.approx.f32 %0, %1;" : "=f"(y) : "f"(x)); return y;
}
__device__ __forceinline__ float sigf(float x) {
    return 0.5f * tanha(0.5f * x) + 0.5f;
}

// cp.async helpers
__device__ __forceinline__ void cp16(unsigned int dst, const void* src) {
    asm volatile("cp.async.ca.shared.global [%0], [%1], 16;"
                 :: "r"(dst), "l"(src));
}
__device__ __forceinline__ void cp_commit() {
    asm volatile("cp.async.commit_group;");
}
__device__ __forceinline__ void cp_wait0() {
    asm volatile("cp.async.wait_group 0;");
}

// bf16 mma m16n8k16, f32 accum (HMMA path — works on plain sm_103)
#define MMA_BF16(d, a, b)                                                     \
    asm volatile(                                                             \
        "mma.sync.aligned.m16n8k16.row.col.f32.bf16.bf16.f32 "                \
        "{%0,%1,%2,%3}, {%4,%5,%6,%7}, {%8,%9}, {%0,%1,%2,%3};"               \
        : "+f"((d)[0]), "+f"((d)[1]), "+f"((d)[2]), "+f"((d)[3])              \
        : "r"((a)[0]), "r"((a)[1]), "r"((a)[2]), "r"((a)[3]),                 \
          "r"((b)[0]), "r"((b)[1]))

// ---------------------------------------------------------------------------
// Prep kernel 1: permuted biases + fc transpose
// ---------------------------------------------------------------------------
__global__ void k_misc(const float* __restrict__ enc_b, const float* __restrict__ dec_b,
                       const float* __restrict__ fc_W,
                       float* __restrict__ encBP, float* __restrict__ decBP,
                       float* __restrict__ fcT) {
    int i = blockIdx.x * 256 + threadIdx.x;
    if (i < 2048) {
        int l = i >> 9, n = i & 511;
        encBP[i] = enc_b[l * 512 + ((n & 3) * 128 + (n >> 2))];
    } else if (i < 4096) {
        int i2 = i - 2048;
        int l = i2 >> 9, n = i2 & 511;
        decBP[i2] = dec_b[l * 512 + ((n & 3) * 128 + (n >> 2))];
    } else if (i < 4096 + H * IN_DIM) {
        int i2 = i - 4096;
        int k = i2 / IN_DIM, j = i2 - k * IN_DIM;
        fcT[i2] = fc_W[j * H + k];
    }
}

// ---------------------------------------------------------------------------
// Prep kernel 2: gate-grouped 4-pack for recurrent kernels
// ---------------------------------------------------------------------------
struct GPJob { const float* s; float* d; int K; };
struct GPJobs { GPJob j[12]; int n; };

__global__ void k_pack4g(GPJobs jobs) {
    int job = blockIdx.y;
    if (job >= jobs.n) return;
    GPJob J = jobs.j[job];
    int i = blockIdx.x * 128 + threadIdx.x;
    if (i < J.K * 128) {
        int k = i >> 7, c = i & 127;
        float4 v;
        v.x = J.s[c * J.K + k];
        v.y = J.s[(128 + c) * J.K + k];
        v.z = J.s[(256 + c) * J.K + k];
        v.w = J.s[(384 + c) * J.K + k];
        ((float4*)J.d)[i] = v;
    }
}

// ---------------------------------------------------------------------------
// Prep kernel 3: GEMM weights -> hi/lo bf16 planes, gate-permuted [n][k]
// grid.y = 0: layer0 (K=48, real 44); 1..3: WihR layers (K=128)
// ---------------------------------------------------------------------------
__global__ void k_wconv(const float* __restrict__ Wih0,
                        const float* __restrict__ WihR,
                        __nv_bfloat16* __restrict__ W0H, __nv_bfloat16* __restrict__ W0L,
                        __nv_bfloat16* __restrict__ WRH, __nv_bfloat16* __restrict__ WRL) {
    int job = blockIdx.y;
    int i = blockIdx.x * 256 + threadIdx.x;
    if (job == 0) {
        if (i < 512 * 48) {
            int n = i / 48, k = i - n * 48;
            float w = 0.f;
            if (k < IN_DIM) w = Wih0[((n & 3) * 128 + (n >> 2)) * IN_DIM + k];
            __nv_bfloat16 hb = __float2bfloat16_rn(w);
            W0H[i] = hb;
            W0L[i] = __float2bfloat16_rn(w - __bfloat162float(hb));
        }
    } else {
        int r = job - 1;
        if (i < 512 * 128) {
            int n = i >> 7, k = i & 127;
            float w = WihR[(long)r * 512 * 128 + ((n & 3) * 128 + (n >> 2)) * 128 + k];
            __nv_bfloat16 hb = __float2bfloat16_rn(w);
            WRH[(long)r * 512 * 128 + i] = hb;
            WRL[(long)r * 512 * 128 + i] = __float2bfloat16_rn(w - __bfloat162float(hb));
        }
    }
}

// ---------------------------------------------------------------------------
// Split-bf16 tensor-core GEMM (mma.sync m16n8k16):
//   out[r][n] = biasP[n] + sum_k A(r,k)*W[n][k],  n gate-permuted upstream.
// Block: M=32 x N=512; 8 warps, warp tile 32x64; K streamed in 16-steps,
// B double-buffered via cp.async. 3 mma passes: Ahi*Bhi + Ahi*Blo + Alo*Bhi.
// smem: B [2 buf][2 split][512][48B rows], A hi/lo [32][K+8], bias[512].
// ---------------------------------------------------------------------------
#define B_ROWB   48
#define B_SPLIT  (512 * B_ROWB)        // 24576 B
#define B_BUF    (2 * B_SPLIT)         // 49152 B
#define B_AREA   (2 * B_BUF)           // 98304 B

template <int K, bool GATHER>
__global__ void __launch_bounds__(256, 1)
k_mmagemm(const float* __restrict__ A,
          const __nv_bfloat16* __restrict__ WH,
          const __nv_bfloat16* __restrict__ WL,
          const float* __restrict__ biasP,
          float* __restrict__ out) {
    extern __shared__ char smc[];
    const int KSTEPS = K / 16;
    const int AP = K + 8;              // padded A row stride (bf16 elems)
    char* Bbase = smc;
    __nv_bfloat16* Ahi = (__nv_bfloat16*)(smc + B_AREA);
    __nv_bfloat16* Alo = Ahi + 32 * AP;
    float* bias_s = (float*)(Alo + 32 * AP);

    const int tid = threadIdx.x;
    const int m0 = blockIdx.x * 32;
    const int w = tid >> 5, lane = tid & 31;

    for (int i = tid; i < 512; i += 256) bias_s[i] = biasP[i];

    // ---- stage A (fp32 -> hi/lo bf16 in smem) ----
    {
        const int row = tid >> 3, cg = tid & 7;
        auto sto = [&](int c, float v0, float v1) {
            __nv_bfloat16 h0 = __float2bfloat16_rn(v0);
            __nv_bfloat16 h1 = __float2bfloat16_rn(v1);
            __nv_bfloat16 l0 = __float2bfloat16_rn(v0 - __bfloat162float(h0));
            __nv_bfloat16 l1 = __float2bfloat16_rn(v1 - __bfloat162float(h1));
            __nv_bfloat162 ph; ph.x = h0; ph.y = h1;
            __nv_bfloat162 pl; pl.x = l0; pl.y = l1;
            *(uint32_t*)&Ahi[row * AP + c] = *(uint32_t*)&ph;
            *(uint32_t*)&Alo[row * AP + c] = *(uint32_t*)&pl;
        };
        if (GATHER) {
            int grow = m0 + row;
            int t = grow >> 11, b = grow & 2047;
            const float* ap = A + ((long)b * SEQ + t) * IN_DIM;
#pragma unroll
            for (int p = 0; p < 3; ++p) {
                int c = cg * 6 + p * 2;
                float v0 = (c < IN_DIM) ? ap[c] : 0.f;
                float v1 = (c + 1 < IN_DIM) ? ap[c + 1] : 0.f;
                sto(c, v0, v1);
            }
        } else {
            const float* ap = A + (long)(m0 + row) * K + cg * 16;
#pragma unroll
            for (int f = 0; f < 4; ++f) {
                float4 q = *(const float4*)(ap + f * 4);
                sto(cg * 16 + f * 4, q.x, q.y);
                sto(cg * 16 + f * 4 + 2, q.z, q.w);
            }
        }
    }

    // ---- B stage lambda (one 16-k slice, both splits) ----
    auto issueB = [&](int ks, int buf) {
#pragma unroll
        for (int it = 0; it < 8; ++it) {
            int idx = tid + it * 256;          // 0..2047
            int split = idx >> 10;
            int rem = idx & 1023;
            int n = rem >> 1, half = rem & 1;
            const __nv_bfloat16* src =
                (split ? WL : WH) + (long)n * K + ks * 16 + half * 8;
            unsigned dst = (unsigned)__cvta_generic_to_shared(
                Bbase + buf * B_BUF + split * B_SPLIT + n * B_ROWB + half * 16);
            cp16(dst, src);
        }
        cp_commit();
    };

    float acc[2][8][4];
#pragma unroll
    for (int mi = 0; mi < 2; ++mi)
#pragma unroll
        for (int ni = 0; ni < 8; ++ni)
#pragma unroll
            for (int q = 0; q < 4; ++q) acc[mi][ni][q] = 0.f;

    issueB(0, 0);
    cp_wait0();
    __syncthreads();   // A, bias, B(0) all visible

    const int ar = lane >> 2, ac = (lane & 3) * 2;
    for (int ks = 0; ks < KSTEPS; ++ks) {
        const int buf = ks & 1;
        const bool more = (ks + 1 < KSTEPS);
        if (more) issueB(ks + 1, buf ^ 1);

        // A fragments (from full-K resident A smem)
        uint32_t ah[2][4], al[2][4];
        const int kb = ks * 16;
#pragma unroll
        for (int mi = 0; mi < 2; ++mi) {
            int r0 = mi * 16 + ar;
            ah[mi][0] = *(const uint32_t*)&Ahi[r0 * AP + kb + ac];
            ah[mi][1] = *(const uint32_t*)&Ahi[(r0 + 8) * AP + kb + ac];
            ah[mi][2] = *(const uint32_t*)&Ahi[r0 * AP + kb + ac + 8];
            ah[mi][3] = *(const uint32_t*)&Ahi[(r0 + 8) * AP + kb + ac + 8];
            al[mi][0] = *(const uint32_t*)&Alo[r0 * AP + kb + ac];
            al[mi][1] = *(const uint32_t*)&Alo[(r0 + 8) * AP + kb + ac];
            al[mi][2] = *(const uint32_t*)&Alo[r0 * AP + kb + ac + 8];
            al[mi][3] = *(const uint32_t*)&Alo[(r0 + 8) * AP + kb + ac + 8];
        }

        const char* Bb = Bbase + buf * B_BUF;
#pragma unroll
        for (int ni = 0; ni < 8; ++ni) {
            int n = w * 64 + ni * 8 + ar;
            const char* rowp = Bb + n * B_ROWB + ac * 2;
            uint32_t bh[2], bl[2];
            bh[0] = *(const uint32_t*)(rowp);
            bh[1] = *(const uint32_t*)(rowp + 16);
            bl[0] = *(const uint32_t*)(rowp + B_SPLIT);
            bl[1] = *(const uint32_t*)(rowp + B_SPLIT + 16);
            MMA_BF16(acc[0][ni], ah[0], bh);
            MMA_BF16(acc[1][ni], ah[1], bh);
            MMA_BF16(acc[0][ni], ah[0], bl);
            MMA_BF16(acc[1][ni], ah[1], bl);
            MMA_BF16(acc[0][ni], al[0], bh);
            MMA_BF16(acc[1][ni], al[1], bh);
        }
        if (more) { cp_wait0(); __syncthreads(); }
    }

    // ---- epilogue: bias + store ----
#pragma unroll
    for (int mi = 0; mi < 2; ++mi) {
        int r = m0 + mi * 16 + ar;
#pragma unroll
        for (int ni = 0; ni < 8; ++ni) {
            int cidx = w * 64 + ni * 8 + ac;
            float b0 = bias_s[cidx], b1 = bias_s[cidx + 1];
            float2 v0 = { acc[mi][ni][0] + b0, acc[mi][ni][1] + b1 };
            float2 v1 = { acc[mi][ni][2] + b0, acc[mi][ni][3] + b1 };
            *(float2*)&out[(long)r * H4 + cidx] = v0;
            *(float2*)&out[(long)(r + 8) * H4 + cidx] = v1;
        }
    }
}

// ---------------------------------------------------------------------------
// Encoder recurrent sweep (unchanged — near FFMA2 floor).
// ---------------------------------------------------------------------------
__global__ void __launch_bounds__(256, 1) k_lstm_seq(const float4* __restrict__ Wp,
                                                     float* __restrict__ ys,
                                                     float* __restrict__ hfin,
                                                     float* __restrict__ cfin) {
    __shared__ float h_s[2][H][TB];
    const int tid = threadIdx.x;
    const int c = tid & 127, bh = tid >> 7;
    const int b0 = blockIdx.x * TB;

    for (int i = tid; i < H * TB; i += 256) (&h_s[1][0][0])[i] = 0.f;
    float c_reg[8] = {0.f, 0.f, 0.f, 0.f, 0.f, 0.f, 0.f, 0.f};
    __syncthreads();

    const float4* wp = Wp + c;
    for (int t = 0; t < SEQ; ++t) {
        const float4* xg = (const float4*)(g_Xg + ((long)t * BATCH + b0) * H4) + c;
        float4 xr[8];
#pragma unroll
        for (int b = 0; b < 8; ++b) xr[b] = xg[(bh * 8 + b) * 128];

        ull acc[4][4];
        ull z = pack2(0.f, 0.f);
#pragma unroll
        for (int g = 0; g < 4; ++g)
#pragma unroll
            for (int p = 0; p < 4; ++p) acc[g][p] = z;

        const float* hp = &h_s[(t + 1) & 1][0][bh * 8];
#pragma unroll 8
        for (int k = 0; k < H; ++k) {
            float4 w = wp[k * 128];
            ulonglong2 hA = *(const ulonglong2*)(hp + k * TB);
            ulonglong2 hB = *(const ulonglong2*)(hp + k * TB + 4);
            ull w0 = pack2(w.x, w.x);
            ffma2(acc[0][0], w0, hA.x); ffma2(acc[0][1], w0, hA.y);
            ffma2(acc[0][2], w0, hB.x); ffma2(acc[0][3], w0, hB.y);
            ull w1 = pack2(w.y, w.y);
            ffma2(acc[1][0], w1, hA.x); ffma2(acc[1][1], w1, hA.y);
            ffma2(acc[1][2], w1, hB.x); ffma2(acc[1][3], w1, hB.y);
            ull w2 = pack2(w.z, w.z);
            ffma2(acc[2][0], w2, hA.x); ffma2(acc[2][1], w2, hA.y);
            ffma2(acc[2][2], w2, hB.x); ffma2(acc[2][3], w2, hB.y);
            ull w3 = pack2(w.w, w.w);
            ffma2(acc[3][0], w3, hA.x); ffma2(acc[3][1], w3, hA.y);
            ffma2(acc[3][2], w3, hB.x); ffma2(acc[3][3], w3, hB.y);
        }
        float hv[8];
#pragma unroll
        for (int p = 0; p < 4; ++p) {
            float i0, i1, f0, f1, g0, g1, o0, o1;
            unpack2(acc[0][p], i0, i1);
            unpack2(acc[1][p], f0, f1);
            unpack2(acc[2][p], g0, g1);
            unpack2(acc[3][p], o0, o1);
            int b = 2 * p;
            {
                float gi = i0 + xr[b].x, gf = f0 + xr[b].y;
                float gg = g0 + xr[b].z, go = o0 + xr[b].w;
                float cn = sigf(gf) * c_reg[b] + sigf(gi) * tanha(gg);
                c_reg[b] = cn;
                hv[b] = sigf(go) * tanha(cn);
            }
            b = 2 * p + 1;
            {
                float gi = i1 + xr[b].x, gf = f1 + xr[b].y;
                float gg = g1 + xr[b].z, go = o1 + xr[b].w;
                float cn = sigf(gf) * c_reg[b] + sigf(gi) * tanha(gg);
                c_reg[b] = cn;
                hv[b] = sigf(go) * tanha(cn);
            }
        }
        float* hw = &h_s[t & 1][c][bh * 8];
        *(float4*)hw       = make_float4(hv[0], hv[1], hv[2], hv[3]);
        *(float4*)(hw + 4) = make_float4(hv[4], hv[5], hv[6], hv[7]);
        float* yp = ys + ((long)t * BATCH + b0 + bh * 8) * H + c;
#pragma unroll
        for (int b = 0; b < 8; ++b) yp[(long)b * H] = hv[b];
        __syncthreads();
    }
#pragma unroll
    for (int b = 0; b < 8; ++b) {
        hfin[(b0 + bh * 8 + b) * H + c] = h_s[1][c][bh * 8 + b];
        cfin[(b0 + bh * 8 + b) * H + c] = c_reg[b];
    }
}

// ---------------------------------------------------------------------------
// Fused decoder (unchanged)
// ---------------------------------------------------------------------------
#define DSM_H   (NL * 2 * H * TB)      // 16384 floats
#define DSM_FCW (H * IN_DIM)           // 5632
#define DSM_DIN (IN_DIM * TB)          // 704
#define DSM_FCB 48
#define DEC_SMEM_BYTES ((DSM_H + DSM_FCW + DSM_DIN + DSM_FCB) * 4)

__global__ void __launch_bounds__(256, 1) k_decoder(const float* __restrict__ x,
                                                    const float* __restrict__ fc_b,
                                                    float* __restrict__ out) {
    extern __shared__ float sm[];
    float* h_s = sm;
    float* fcw = sm + DSM_H;
    float* din = fcw + DSM_FCW;
    float* fcb = din + DSM_DIN;

    const int tid = threadIdx.x;
    const int c = tid & 127, bh = tid >> 7;
    const int b0 = blockIdx.x * TB;

    for (int i = tid; i < NL * H * TB; i += 256) {
        int l = i / (H * TB);
        int r = i - l * (H * TB);
        int k = r / TB, b = r - k * TB;
        h_s[((l * 2 + 1) * H + k) * TB + b] = g_h[((long)l * BATCH + b0 + b) * H + k];
    }
    float c_reg[NL * 8];
#pragma unroll
    for (int l = 0; l < NL; ++l)
#pragma unroll
        for (int b = 0; b < 8; ++b)
            c_reg[l * 8 + b] = g_c[((long)l * BATCH + b0 + bh * 8 + b) * H + c];
    for (int i = tid; i < DSM_FCW; i += 256) fcw[i] = g_fcT[i];
    for (int i = tid; i < IN_DIM * TB; i += 256) {
        int k = i >> 4, b = i & 15;
        din[i] = x[((long)(b0 + b) * SEQ + (SEQ - 1)) * IN_DIM + k];
    }
    for (int i = tid; i < IN_DIM; i += 256) fcb[i] = fc_b[i];
    __syncthreads();

    float4 bias[NL];
#pragma unroll
    for (int l = 0; l < NL; ++l)
        bias[l] = *(const float4*)&g_decBP[l * H4 + 4 * c];

    for (int t = 0; t < TDEC; ++t) {
        const int cur = t & 1, prv = cur ^ 1;
#pragma unroll 1
        for (int l = 0; l < NL; ++l) {
            ull acc[4][4];
            ull z = pack2(0.f, 0.f);
#pragma unroll
            for (int g = 0; g < 4; ++g)
#pragma unroll
                for (int p = 0; p < 4; ++p) acc[g][p] = z;

            {
                const float4* wr = (const float4*)g_decWhhP4 + (long)l * H * H + c;
                const float* hp = &h_s[(l * 2 + prv) * H * TB + bh * 8];
#pragma unroll 8
                for (int k = 0; k < H; ++k) {
                    float4 w = wr[k * 128];
                    ulonglong2 hA = *(const ulonglong2*)(hp + k * TB);
                    ulonglong2 hB = *(const ulonglong2*)(hp + k * TB + 4);
                    ull w0 = pack2(w.x, w.x);
                    ffma2(acc[0][0], w0, hA.x); ffma2(acc[0][1], w0, hA.y);
                    ffma2(acc[0][2], w0, hB.x); ffma2(acc[0][3], w0, hB.y);
                    ull w1 = pack2(w.y, w.y);
                    ffma2(acc[1][0], w1, hA.x); ffma2(acc[1][1], w1, hA.y);
                    ffma2(acc[1][2], w1, hB.x); ffma2(acc[1][3], w1, hB.y);
                    ull w2 = pack2(w.z, w.z);
                    ffma2(acc[2][0], w2, hA.x); ffma2(acc[2][1], w2, hA.y);
                    ffma2(acc[2][2], w2, hB.x); ffma2(acc[2][3], w2, hB.y);
                    ull w3 = pack2(w.w, w.w);
                    ffma2(acc[3][0], w3, hA.x); ffma2(acc[3][1], w3, hA.y);
                    ffma2(acc[3][2], w3, hB.x); ffma2(acc[3][3], w3, hB.y);
                }
            }
            if (l == 0) {
                const float4* wi = (const float4*)g_decWih0P4 + c;
                const float* dp = din + bh * 8;
#pragma unroll 4
                for (int k = 0; k < IN_DIM; ++k) {
                    float4 w = wi[k * 128];
                    ulonglong2 dA = *(const ulonglong2*)(dp + k * TB);
                    ulonglong2 dB = *(const ulonglong2*)(dp + k * TB + 4);
                    ull w0 = pack2(w.x, w.x);
                    ffma2(acc[0][0], w0, dA.x); ffma2(acc[0][1], w0, dA.y);
                    ffma2(acc[0][2], w0, dB.x); ffma2(acc[0][3], w0, dB.y);
                    ull w1 = pack2(w.y, w.y);
                    ffma2(acc[1][0], w1, dA.x); ffma2(acc[1][1], w1, dA.y);
                    ffma2(acc[1][2], w1, dB.x); ffma2(acc[1][3], w1, dB.y);
                    ull w2 = pack2(w.z, w.z);
                    ffma2(acc[2][0], w2, dA.x); ffma2(acc[2][1], w2, dA.y);
                    ffma2(acc[2][2], w2, dB.x); ffma2(acc[2][3], w2, dB.y);
                    ull w3 = pack2(w.w, w.w);
                    ffma2(acc[3][0], w3, dA.x); ffma2(acc[3][1], w3, dA.y);
                    ffma2(acc[3][2], w3, dB.x); ffma2(acc[3][3], w3, dB.y);
                }
            } else {
                const float4* wi = (const float4*)g_decWihRP4 + (long)(l - 1) * H * H + c;
                const float* hp2 = &h_s[((l - 1) * 2 + cur) * H * TB + bh * 8];
#pragma unroll 8
                for (int k = 0; k < H; ++k) {
                    float4 w = wi[k * 128];
                    ulonglong2 hA = *(const ulonglong2*)(hp2 + k * TB);
                    ulonglong2 hB = *(const ulonglong2*)(hp2 + k * TB + 4);
                    ull w0 = pack2(w.x, w.x);
                    ffma2(acc[0][0], w0, hA.x); ffma2(acc[0][1], w0, hA.y);
                    ffma2(acc[0][2], w0, hB.x); ffma2(acc[0][3], w0, hB.y);
                    ull w1 = pack2(w.y, w.y);
                    ffma2(acc[1][0], w1, hA.x); ffma2(acc[1][1], w1, hA.y);
                    ffma2(acc[1][2], w1, hB.x); ffma2(acc[1][3], w1, hB.y);
                    ull w2 = pack2(w.z, w.z);
                    ffma2(acc[2][0], w2, hA.x); ffma2(acc[2][1], w2, hA.y);
                    ffma2(acc[2][2], w2, hB.x); ffma2(acc[2][3], w2, hB.y);
                    ull w3 = pack2(w.w, w.w);
                    ffma2(acc[3][0], w3, hA.x); ffma2(acc[3][1], w3, hA.y);
                    ffma2(acc[3][2], w3, hB.x); ffma2(acc[3][3], w3, hB.y);
                }
            }
            float4 bb = bias[l];
            float hv[8];
#pragma unroll
            for (int p = 0; p < 4; ++p) {
                float i0, i1, f0, f1, g0, g1, o0, o1;
                unpack2(acc[0][p], i0, i1);
                unpack2(acc[1][p], f0, f1);
                unpack2(acc[2][p], g0, g1);
                unpack2(acc[3][p], o0, o1);
                int b = 2 * p;
                {
                    float gi = i0 + bb.x, gf = f0 + bb.y, gg = g0 + bb.z, go = o0 + bb.w;
                    float cn = sigf(gf) * c_reg[l * 8 + b] + sigf(gi) * tanha(gg);
                    c_reg[l * 8 + b] = cn;
                    hv[b] = sigf(go) * tanha(cn);
                }
                b = 2 * p + 1;
                {
                    float gi = i1 + bb.x, gf = f1 + bb.y, gg = g1 + bb.z, go = o1 + bb.w;
                    float cn = sigf(gf) * c_reg[l * 8 + b] + sigf(gi) * tanha(gg);
                    c_reg[l * 8 + b] = cn;
                    hv[b] = sigf(go) * tanha(cn);
                }
            }
            float* hw = &h_s[((l * 2 + cur) * H + c) * TB + bh * 8];
            *(float4*)hw       = make_float4(hv[0], hv[1], hv[2], hv[3]);
            *(float4*)(hw + 4) = make_float4(hv[4], hv[5], hv[6], hv[7]);
            __syncthreads();
        }
        const float* h3 = &h_s[(3 * 2 + cur) * H * TB];
        for (int idx = tid; idx < TB * IN_DIM; idx += 256) {
            int b = idx / IN_DIM, j = idx - b * IN_DIM;
            float s = fcb[j];
#pragma unroll 8
            for (int k = 0; k < H; ++k)
                s += h3[k * TB + b] * fcw[k * IN_DIM + j];
            out[((long)(b0 + b) * TDEC + t) * IN_DIM + j] = s;
            din[j * TB + b] = s;
        }
        __syncthreads();
    }
}

// ---------------------------------------------------------------------------
// Host launcher
// ---------------------------------------------------------------------------
extern "C" void kernel_launch(void* const* d_in, const int* in_sizes, int n_in,
                              void* d_out, int out_size) {
    const float* x        = (const float*)d_in[0];
    const float* enc_Wih0 = (const float*)d_in[2];
    const float* enc_WihR = (const float*)d_in[3];
    const float* enc_Whh  = (const float*)d_in[4];
    const float* enc_b    = (const float*)d_in[5];
    const float* dec_Wih0 = (const float*)d_in[6];
    const float* dec_WihR = (const float*)d_in[7];
    const float* dec_Whh  = (const float*)d_in[8];
    const float* dec_b    = (const float*)d_in[9];
    const float* fc_W     = (const float*)d_in[10];
    const float* fc_b     = (const float*)d_in[11];
    float* out = (float*)d_out;

    float *encBP, *decBP;
    float *encWhhP4, *decWhhP4, *decWihRP4, *decWih0P4, *fcT;
    float *Xg, *ys, *hSt, *cSt;
    __nv_bfloat16 *W0H, *W0L, *WRH, *WRL;
    cudaGetSymbolAddress((void**)&encBP,     g_encBP);
    cudaGetSymbolAddress((void**)&decBP,     g_decBP);
    cudaGetSymbolAddress((void**)&encWhhP4,  g_encWhhP4);
    cudaGetSymbolAddress((void**)&decWhhP4,  g_decWhhP4);
    cudaGetSymbolAddress((void**)&decWihRP4, g_decWihRP4);
    cudaGetSymbolAddress((void**)&decWih0P4, g_decWih0P4);
    cudaGetSymbolAddress((void**)&fcT,       g_fcT);
    cudaGetSymbolAddress((void**)&Xg,        g_Xg);
    cudaGetSymbolAddress((void**)&ys,        g_ys);
    cudaGetSymbolAddress((void**)&hSt,       g_h);
    cudaGetSymbolAddress((void**)&cSt,       g_c);
    cudaGetSymbolAddress((void**)&W0H,       g_W0H);
    cudaGetSymbolAddress((void**)&W0L,       g_W0L);
    cudaGetSymbolAddress((void**)&WRH,       g_WRH);
    cudaGetSymbolAddress((void**)&WRL,       g_WRL);

    cudaFuncSetAttribute(k_decoder, cudaFuncAttributeMaxDynamicSharedMemorySize,
                         DEC_SMEM_BYTES);
    const int DYN48  = B_AREA + 2 * 32 * (48 + 8) * 2 + 2048;    // 107520
    const int DYN128 = B_AREA + 2 * 32 * (128 + 8) * 2 + 2048;   // 117760
    cudaFuncSetAttribute(k_mmagemm<48, true>,
                         cudaFuncAttributeMaxDynamicSharedMemorySize, DYN48);
    cudaFuncSetAttribute(k_mmagemm<128, false>,
                         cudaFuncAttributeMaxDynamicSharedMemorySize, DYN128);

    // prep
    k_misc<<<(4096 + H * IN_DIM + 255) / 256, 256>>>(enc_b, dec_b, fc_W,
                                                     encBP, decBP, fcT);
    {
        GPJobs jg; jg.n = 12;
        for (int l = 0; l < NL; ++l)
            jg.j[l] = { enc_Whh + (long)l * H4 * H, encWhhP4 + (long)l * H * H * 4, H };
        for (int l = 0; l < NL; ++l)
            jg.j[4 + l] = { dec_Whh + (long)l * H4 * H, decWhhP4 + (long)l * H * H * 4, H };
        for (int r = 0; r < 3; ++r)
            jg.j[8 + r] = { dec_WihR + (long)r * H4 * H, decWihRP4 + (long)r * H * H * 4, H };
        jg.j[11] = { dec_Wih0, decWih0P4, IN_DIM };
        dim3 g(128, 12);
        k_pack4g<<<g, 128>>>(jg);
    }
    {
        dim3 g(256, 4);
        k_wconv<<<g, 256>>>(enc_Wih0, enc_WihR, W0H, W0L, WRH, WRL);
    }

    const int MT32 = SEQ * BATCH / 32;   // 12800

    // encoder layer 0
    k_mmagemm<48, true><<<MT32, 256, DYN48>>>(x, W0H, W0L, encBP, Xg);
    k_lstm_seq<<<BATCH / TB, 256>>>((const float4*)encWhhP4, ys, hSt, cSt);
    // encoder layers 1..3
    for (int l = 1; l < NL; ++l) {
        k_mmagemm<128, false><<<MT32, 256, DYN128>>>(
            ys, WRH + (long)(l - 1) * 512 * 128, WRL + (long)(l - 1) * 512 * 128,
            encBP + (long)l * H4, Xg);
        k_lstm_seq<<<BATCH / TB, 256>>>((const float4*)(encWhhP4 + (long)l * H * H * 4),
                                        ys, hSt + (long)l * BATCH * H,
                                        cSt + (long)l * BATCH * H);
    }
    // fused decoder
    k_decoder<<<BATCH / TB, 256, DEC_SMEM_BYTES>>>(x, fc_b, out);
}

// round 10
// speedup vs baseline: 1.6704x; 1.1615x over previous
#include <cuda_runtime.h>
#include <cuda_bf16.h>
#include <cstdint>
#include <math.h>

// Problem constants
#define IN_DIM 44
#define H      128
#define H4     512
#define NL     4
#define TDEC   50
#define BATCH  2048
#define SEQ    200

#define TB  16   // batch tile per block (both recurrent kernels)
#define NROWS (SEQ * BATCH)        // 409600 GEMM rows
#define MT64  (NROWS / 64)         // 6400 m-tiles
#define GBX   74                   // GEMM persistent blocks per N-half

typedef unsigned long long ull;
typedef __nv_bfloat16 bf16;

// ---------------------------------------------------------------------------
// Device scratch
// ---------------------------------------------------------------------------
__device__ float g_Xg[(long)NROWS * H4];        // gate-interleaved: [row][4c+g]
__device__ bf16  g_ysH[(long)NROWS * H];        // layer output hi plane [row][k]
__device__ bf16  g_ysL[(long)NROWS * H];        // layer output lo plane
__device__ bf16  g_x0H[(long)NROWS * 48];       // gathered x hi plane [row][48]
__device__ bf16  g_x0L[(long)NROWS * 48];
__device__ float g_h[NL * BATCH * H];
__device__ float g_c[NL * BATCH * H];
// permuted biases [l][4c+g]
__device__ float g_encBP[NL * H4];
__device__ float g_decBP[NL * H4];
// gate-grouped packed recurrent/input weights: float4[k*128+c] = {Wi,Wf,Wg,Wo}[c][k]
__device__ float g_encWhhP4[NL * H * H * 4];
__device__ float g_decWhhP4[NL * H * H * 4];
__device__ float g_decWihRP4[3 * H * H * 4];
__device__ float g_decWih0P4[IN_DIM * H * 4];
__device__ float g_fcT[H * IN_DIM];
// bf16 hi/lo GEMM weight planes, gate-permuted [n][k] (k padded)
__device__ bf16 g_W0H[512 * 48];
__device__ bf16 g_W0L[512 * 48];
__device__ bf16 g_WRH[3 * 512 * 128];
__device__ bf16 g_WRL[3 * 512 * 128];

// ---------------------------------------------------------------------------
// packed f32x2 helpers
// ---------------------------------------------------------------------------
__device__ __forceinline__ ull pack2(float a, float b) {
    ull r; asm("mov.b64 %0, {%1,%2};" : "=l"(r) : "f"(a), "f"(b)); return r;
}
__device__ __forceinline__ void unpack2(ull v, float& a, float& b) {
    asm("mov.b64 {%0,%1}, %2;" : "=f"(a), "=f"(b) : "l"(v));
}
__device__ __forceinline__ void ffma2(ull& d, ull a, ull b) {
    asm("fma.rn.f32x2 %0, %1, %2, %0;" : "+l"(d) : "l"(a), "l"(b));
}

// activations via MUFU.TANH
__device__ __forceinline__ float tanha(float x) {
    float y; asm("tanh.approx.f32 %0, %1;" : "=f"(y) : "f"(x)); return y;
}
__device__ __forceinline__ float sigf(float x) {
    return 0.5f * tanha(0.5f * x) + 0.5f;
}

// cp.async helpers
__device__ __forceinline__ void cp16(unsigned int dst, const void* src) {
    asm volatile("cp.async.ca.shared.global [%0], [%1], 16;"
                 :: "r"(dst), "l"(src));
}
__device__ __forceinline__ void cp_commit() {
    asm volatile("cp.async.commit_group;");
}
__device__ __forceinline__ void cp_wait0() {
    asm volatile("cp.async.wait_group 0;");
}

// bf16 mma m16n8k16, f32 accum (HMMA path — works on plain sm_103)
#define MMA_BF16(d, a, b)                                                     \
    asm volatile(                                                             \
        "mma.sync.aligned.m16n8k16.row.col.f32.bf16.bf16.f32 "                \
        "{%0,%1,%2,%3}, {%4,%5,%6,%7}, {%8,%9}, {%0,%1,%2,%3};"               \
        : "+f"((d)[0]), "+f"((d)[1]), "+f"((d)[2]), "+f"((d)[3])              \
        : "r"((a)[0]), "r"((a)[1]), "r"((a)[2]), "r"((a)[3]),                 \
          "r"((b)[0]), "r"((b)[1]))

__device__ __forceinline__ void split_bf16(float v, bf16& h, bf16& l) {
    h = __float2bfloat16_rn(v);
    l = __float2bfloat16_rn(v - __bfloat162float(h));
}

// ---------------------------------------------------------------------------
// Prep kernel 1: permuted biases + fc transpose
// ---------------------------------------------------------------------------
__global__ void k_misc(const float* __restrict__ enc_b, const float* __restrict__ dec_b,
                       const float* __restrict__ fc_W,
                       float* __restrict__ encBP, float* __restrict__ decBP,
                       float* __restrict__ fcT) {
    int i = blockIdx.x * 256 + threadIdx.x;
    if (i < 2048) {
        int l = i >> 9, n = i & 511;
        encBP[i] = enc_b[l * 512 + ((n & 3) * 128 + (n >> 2))];
    } else if (i < 4096) {
        int i2 = i - 2048;
        int l = i2 >> 9, n = i2 & 511;
        decBP[i2] = dec_b[l * 512 + ((n & 3) * 128 + (n >> 2))];
    } else if (i < 4096 + H * IN_DIM) {
        int i2 = i - 4096;
        int k = i2 / IN_DIM, j = i2 - k * IN_DIM;
        fcT[i2] = fc_W[j * H + k];
    }
}

// ---------------------------------------------------------------------------
// Prep kernel 2: gate-grouped 4-pack for recurrent kernels
// ---------------------------------------------------------------------------
struct GPJob { const float* s; float* d; int K; };
struct GPJobs { GPJob j[12]; int n; };

__global__ void k_pack4g(GPJobs jobs) {
    int job = blockIdx.y;
    if (job >= jobs.n) return;
    GPJob J = jobs.j[job];
    int i = blockIdx.x * 128 + threadIdx.x;
    if (i < J.K * 128) {
        int k = i >> 7, c = i & 127;
        float4 v;
        v.x = J.s[c * J.K + k];
        v.y = J.s[(128 + c) * J.K + k];
        v.z = J.s[(256 + c) * J.K + k];
        v.w = J.s[(384 + c) * J.K + k];
        ((float4*)J.d)[i] = v;
    }
}

// ---------------------------------------------------------------------------
// Prep kernel 3: GEMM weights -> hi/lo bf16 planes, gate-permuted [n][k]
// ---------------------------------------------------------------------------
__global__ void k_wconv(const float* __restrict__ Wih0,
                        const float* __restrict__ WihR,
                        bf16* __restrict__ W0H, bf16* __restrict__ W0L,
                        bf16* __restrict__ WRH, bf16* __restrict__ WRL) {
    int job = blockIdx.y;
    int i = blockIdx.x * 256 + threadIdx.x;
    if (job == 0) {
        if (i < 512 * 48) {
            int n = i / 48, k = i - n * 48;
            float w = 0.f;
            if (k < IN_DIM) w = Wih0[((n & 3) * 128 + (n >> 2)) * IN_DIM + k];
            split_bf16(w, W0H[i], W0L[i]);
        }
    } else {
        int r = job - 1;
        if (i < 512 * 128) {
            int n = i >> 7, k = i & 127;
            float w = WihR[(long)r * 512 * 128 + ((n & 3) * 128 + (n >> 2)) * 128 + k];
            split_bf16(w, WRH[(long)r * 512 * 128 + i], WRL[(long)r * 512 * 128 + i]);
        }
    }
}

// ---------------------------------------------------------------------------
// Prep kernel 4: gather x -> hi/lo bf16 [row][48] (row = t*BATCH + b)
// ---------------------------------------------------------------------------
__global__ void k_xconv(const float* __restrict__ x,
                        bf16* __restrict__ XH, bf16* __restrict__ XL) {
    for (long i = (long)blockIdx.x * 256 + threadIdx.x; i < (long)NROWS * 48;
         i += (long)gridDim.x * 256) {
        int row = (int)(i / 48), k = (int)(i - (long)row * 48);
        int t = row >> 11, b = row & 2047;
        float v = (k < IN_DIM) ? x[((long)b * SEQ + t) * IN_DIM + k] : 0.f;
        split_bf16(v, XH[i], XL[i]);
    }
}

// ---------------------------------------------------------------------------
// Persistent weight-resident split-bf16 tensor-core GEMM.
//   out[r][n0+n] = biasP[n0+n] + sum_k A(r,k)*W[n0+n][k]
// grid (74, 2): 148 blocks, 1/SM. B (hi/lo) resident in smem; A (pre-split
// bf16 planes) streamed in M=64 tiles via cp.async double buffer.
// 8 warps = 2(M)x4(N); warp tile 32x64; 3 mma passes per k-step.
// ---------------------------------------------------------------------------
template <int K>
__global__ void __launch_bounds__(256, 1)
k_mmagemm(const bf16* __restrict__ AH, const bf16* __restrict__ AL,
          const bf16* __restrict__ WH, const bf16* __restrict__ WL,
          const float* __restrict__ biasP, float* __restrict__ out) {
    extern __shared__ char smc[];
    const int KSTEPS = K / 16;
    const int ROWB = (K + 8) * 2;          // padded row bytes
    const int BSP  = 256 * ROWB;           // one B split plane
    const int ASP  = 64 * ROWB;            // one A split plane
    const int CPR  = K / 8;                // 16B chunks per row

    char* Bb = smc;                        // [2 split][256][ROWB]
    char* Ab = smc + 2 * BSP;              // [2 buf][2 split][64][ROWB]
    float* bias_s = (float*)(smc + 2 * BSP + 4 * ASP);

    const int tid = threadIdx.x;
    const int n0 = blockIdx.y * 256;
    const int w = tid >> 5, lane = tid & 31;
    const int wm = w >> 2, wn = w & 3;
    const int ar = lane >> 2, ac = (lane & 3) * 2;

    for (int i = tid; i < 256; i += 256) bias_s[i] = biasP[n0 + i];

    // ---- stage B (resident, once) ----
    {
        const int total = 2 * 256 * CPR;
        for (int i = tid; i < total; i += 256) {
            int split = i / (256 * CPR);
            int rem = i - split * 256 * CPR;
            int n = rem / CPR, ch = rem - n * CPR;
            const bf16* src = (split ? WL : WH) + (long)(n0 + n) * K + ch * 8;
            unsigned dst = (unsigned)__cvta_generic_to_shared(
                Bb + split * BSP + n * ROWB + ch * 16);
            cp16(dst, src);
        }
        cp_commit();
    }

    // ---- A stage lambda ----
    auto issueA = [&](int mt, int buf) {
        const int total = 2 * 64 * CPR;
        for (int i = tid; i < total; i += 256) {
            int split = i / (64 * CPR);
            int rem = i - split * 64 * CPR;
            int row = rem / CPR, ch = rem - row * CPR;
            const bf16* src = (split ? AL : AH) + (long)(mt * 64 + row) * K + ch * 8;
            unsigned dst = (unsigned)__cvta_generic_to_shared(
                Ab + buf * 2 * ASP + split * ASP + row * ROWB + ch * 16);
            cp16(dst, src);
        }
        cp_commit();
    };

    issueA(blockIdx.x, 0);
    cp_wait0();
    __syncthreads();

    const bf16* Ahi0 = (const bf16*)Ab;
    int it = 0;
    for (int mt = blockIdx.x; mt < MT64; mt += GBX, ++it) {
        const int buf = it & 1;
        const bool more = (mt + GBX < MT64);
        if (more) issueA(mt + GBX, buf ^ 1);

        const char* Ahb = Ab + buf * 2 * ASP;
        const char* Alb = Ahb + ASP;

        float acc[2][8][4];
#pragma unroll
        for (int mi = 0; mi < 2; ++mi)
#pragma unroll
            for (int ni = 0; ni < 8; ++ni)
#pragma unroll
                for (int q = 0; q < 4; ++q) acc[mi][ni][q] = 0.f;

        for (int ks = 0; ks < KSTEPS; ++ks) {
            const int kb = ks * 16;
            uint32_t ah[2][4], al[2][4];
#pragma unroll
            for (int mi = 0; mi < 2; ++mi) {
                int r0 = wm * 32 + mi * 16 + ar;
                const char* ph = Ahb + r0 * ROWB + (kb + ac) * 2;
                const char* pl = Alb + r0 * ROWB + (kb + ac) * 2;
                ah[mi][0] = *(const uint32_t*)(ph);
                ah[mi][1] = *(const uint32_t*)(ph + 8 * ROWB);
                ah[mi][2] = *(const uint32_t*)(ph + 16);
                ah[mi][3] = *(const uint32_t*)(ph + 8 * ROWB + 16);
                al[mi][0] = *(const uint32_t*)(pl);
                al[mi][1] = *(const uint32_t*)(pl + 8 * ROWB);
                al[mi][2] = *(const uint32_t*)(pl + 16);
                al[mi][3] = *(const uint32_t*)(pl + 8 * ROWB + 16);
            }
#pragma unroll
            for (int ni = 0; ni < 8; ++ni) {
                int n = wn * 64 + ni * 8 + ar;
                const char* rowp = Bb + n * ROWB + (kb + ac) * 2;
                uint32_t bh[2], bl[2];
                bh[0] = *(const uint32_t*)(rowp);
                bh[1] = *(const uint32_t*)(rowp + 16);
                bl[0] = *(const uint32_t*)(rowp + BSP);
                bl[1] = *(const uint32_t*)(rowp + BSP + 16);
                MMA_BF16(acc[0][ni], ah[0], bh);
                MMA_BF16(acc[1][ni], ah[1], bh);
                MMA_BF16(acc[0][ni], ah[0], bl);
                MMA_BF16(acc[1][ni], ah[1], bl);
                MMA_BF16(acc[0][ni], al[0], bh);
                MMA_BF16(acc[1][ni], al[1], bh);
            }
        }

        // ---- epilogue: bias + store ----
        const int m0 = mt * 64;
#pragma unroll
        for (int mi = 0; mi < 2; ++mi) {
            int r = m0 + wm * 32 + mi * 16 + ar;
#pragma unroll
            for (int ni = 0; ni < 8; ++ni) {
                int cl = wn * 64 + ni * 8 + ac;
                float b0 = bias_s[cl], b1 = bias_s[cl + 1];
                float2 v0 = { acc[mi][ni][0] + b0, acc[mi][ni][1] + b1 };
                float2 v1 = { acc[mi][ni][2] + b0, acc[mi][ni][3] + b1 };
                *(float2*)&out[(long)r * H4 + n0 + cl] = v0;
                *(float2*)&out[(long)(r + 8) * H4 + n0 + cl] = v1;
            }
        }
        if (more) { cp_wait0(); __syncthreads(); }
    }
}

// ---------------------------------------------------------------------------
// Encoder recurrent sweep; writes hi/lo bf16 ys planes for the next GEMM.
// ---------------------------------------------------------------------------
template <bool WRITE_YS>
__global__ void __launch_bounds__(256, 1) k_lstm_seq(const float4* __restrict__ Wp,
                                                     bf16* __restrict__ ysH,
                                                     bf16* __restrict__ ysL,
                                                     float* __restrict__ hfin,
                                                     float* __restrict__ cfin) {
    __shared__ float h_s[2][H][TB];
    const int tid = threadIdx.x;
    const int c = tid & 127, bh = tid >> 7;
    const int b0 = blockIdx.x * TB;

    for (int i = tid; i < H * TB; i += 256) (&h_s[1][0][0])[i] = 0.f;
    float c_reg[8] = {0.f, 0.f, 0.f, 0.f, 0.f, 0.f, 0.f, 0.f};
    __syncthreads();

    const float4* wp = Wp + c;
    for (int t = 0; t < SEQ; ++t) {
        const float4* xg = (const float4*)(g_Xg + ((long)t * BATCH + b0) * H4) + c;
        float4 xr[8];
#pragma unroll
        for (int b = 0; b < 8; ++b) xr[b] = xg[(bh * 8 + b) * 128];

        ull acc[4][4];
        ull z = pack2(0.f, 0.f);
#pragma unroll
        for (int g = 0; g < 4; ++g)
#pragma unroll
            for (int p = 0; p < 4; ++p) acc[g][p] = z;

        const float* hp = &h_s[(t + 1) & 1][0][bh * 8];
#pragma unroll 8
        for (int k = 0; k < H; ++k) {
            float4 w = wp[k * 128];
            ulonglong2 hA = *(const ulonglong2*)(hp + k * TB);
            ulonglong2 hB = *(const ulonglong2*)(hp + k * TB + 4);
            ull w0 = pack2(w.x, w.x);
            ffma2(acc[0][0], w0, hA.x); ffma2(acc[0][1], w0, hA.y);
            ffma2(acc[0][2], w0, hB.x); ffma2(acc[0][3], w0, hB.y);
            ull w1 = pack2(w.y, w.y);
            ffma2(acc[1][0], w1, hA.x); ffma2(acc[1][1], w1, hA.y);
            ffma2(acc[1][2], w1, hB.x); ffma2(acc[1][3], w1, hB.y);
            ull w2 = pack2(w.z, w.z);
            ffma2(acc[2][0], w2, hA.x); ffma2(acc[2][1], w2, hA.y);
            ffma2(acc[2][2], w2, hB.x); ffma2(acc[2][3], w2, hB.y);
            ull w3 = pack2(w.w, w.w);
            ffma2(acc[3][0], w3, hA.x); ffma2(acc[3][1], w3, hA.y);
            ffma2(acc[3][2], w3, hB.x); ffma2(acc[3][3], w3, hB.y);
        }
        float hv[8];
#pragma unroll
        for (int p = 0; p < 4; ++p) {
            float i0, i1, f0, f1, g0, g1, o0, o1;
            unpack2(acc[0][p], i0, i1);
            unpack2(acc[1][p], f0, f1);
            unpack2(acc[2][p], g0, g1);
            unpack2(acc[3][p], o0, o1);
            int b = 2 * p;
            {
                float gi = i0 + xr[b].x, gf = f0 + xr[b].y;
                float gg = g0 + xr[b].z, go = o0 + xr[b].w;
                float cn = sigf(gf) * c_reg[b] + sigf(gi) * tanha(gg);
                c_reg[b] = cn;
                hv[b] = sigf(go) * tanha(cn);
            }
            b = 2 * p + 1;
            {
                float gi = i1 + xr[b].x, gf = f1 + xr[b].y;
                float gg = g1 + xr[b].z, go = o1 + xr[b].w;
                float cn = sigf(gf) * c_reg[b] + sigf(gi) * tanha(gg);
                c_reg[b] = cn;
                hv[b] = sigf(go) * tanha(cn);
            }
        }
        float* hw = &h_s[t & 1][c][bh * 8];
        *(float4*)hw       = make_float4(hv[0], hv[1], hv[2], hv[3]);
        *(float4*)(hw + 4) = make_float4(hv[4], hv[5], hv[6], hv[7]);
        if (WRITE_YS) {
            long base = ((long)t * BATCH + b0 + bh * 8) * H + c;
#pragma unroll
            for (int b = 0; b < 8; ++b) {
                bf16 hh, hl;
                split_bf16(hv[b], hh, hl);
                ysH[base + (long)b * H] = hh;
                ysL[base + (long)b * H] = hl;
            }
        }
        __syncthreads();
    }
#pragma unroll
    for (int b = 0; b < 8; ++b) {
        hfin[(b0 + bh * 8 + b) * H + c] = h_s[1][c][bh * 8 + b];
        cfin[(b0 + bh * 8 + b) * H + c] = c_reg[b];
    }
}

// ---------------------------------------------------------------------------
// Fused decoder (unchanged)
// ---------------------------------------------------------------------------
#define DSM_H   (NL * 2 * H * TB)      // 16384 floats
#define DSM_FCW (H * IN_DIM)           // 5632
#define DSM_DIN (IN_DIM * TB)          // 704
#define DSM_FCB 48
#define DEC_SMEM_BYTES ((DSM_H + DSM_FCW + DSM_DIN + DSM_FCB) * 4)

__global__ void __launch_bounds__(256, 1) k_decoder(const float* __restrict__ x,
                                                    const float* __restrict__ fc_b,
                                                    float* __restrict__ out) {
    extern __shared__ float sm[];
    float* h_s = sm;
    float* fcw = sm + DSM_H;
    float* din = fcw + DSM_FCW;
    float* fcb = din + DSM_DIN;

    const int tid = threadIdx.x;
    const int c = tid & 127, bh = tid >> 7;
    const int b0 = blockIdx.x * TB;

    for (int i = tid; i < NL * H * TB; i += 256) {
        int l = i / (H * TB);
        int r = i - l * (H * TB);
        int k = r / TB, b = r - k * TB;
        h_s[((l * 2 + 1) * H + k) * TB + b] = g_h[((long)l * BATCH + b0 + b) * H + k];
    }
    float c_reg[NL * 8];
#pragma unroll
    for (int l = 0; l < NL; ++l)
#pragma unroll
        for (int b = 0; b < 8; ++b)
            c_reg[l * 8 + b] = g_c[((long)l * BATCH + b0 + bh * 8 + b) * H + c];
    for (int i = tid; i < DSM_FCW; i += 256) fcw[i] = g_fcT[i];
    for (int i = tid; i < IN_DIM * TB; i += 256) {
        int k = i >> 4, b = i & 15;
        din[i] = x[((long)(b0 + b) * SEQ + (SEQ - 1)) * IN_DIM + k];
    }
    for (int i = tid; i < IN_DIM; i += 256) fcb[i] = fc_b[i];
    __syncthreads();

    float4 bias[NL];
#pragma unroll
    for (int l = 0; l < NL; ++l)
        bias[l] = *(const float4*)&g_decBP[l * H4 + 4 * c];

    for (int t = 0; t < TDEC; ++t) {
        const int cur = t & 1, prv = cur ^ 1;
#pragma unroll 1
        for (int l = 0; l < NL; ++l) {
            ull acc[4][4];
            ull z = pack2(0.f, 0.f);
#pragma unroll
            for (int g = 0; g < 4; ++g)
#pragma unroll
                for (int p = 0; p < 4; ++p) acc[g][p] = z;

            {
                const float4* wr = (const float4*)g_decWhhP4 + (long)l * H * H + c;
                const float* hp = &h_s[(l * 2 + prv) * H * TB + bh * 8];
#pragma unroll 8
                for (int k = 0; k < H; ++k) {
                    float4 w = wr[k * 128];
                    ulonglong2 hA = *(const ulonglong2*)(hp + k * TB);
                    ulonglong2 hB = *(const ulonglong2*)(hp + k * TB + 4);
                    ull w0 = pack2(w.x, w.x);
                    ffma2(acc[0][0], w0, hA.x); ffma2(acc[0][1], w0, hA.y);
                    ffma2(acc[0][2], w0, hB.x); ffma2(acc[0][3], w0, hB.y);
                    ull w1 = pack2(w.y, w.y);
                    ffma2(acc[1][0], w1, hA.x); ffma2(acc[1][1], w1, hA.y);
                    ffma2(acc[1][2], w1, hB.x); ffma2(acc[1][3], w1, hB.y);
                    ull w2 = pack2(w.z, w.z);
                    ffma2(acc[2][0], w2, hA.x); ffma2(acc[2][1], w2, hA.y);
                    ffma2(acc[2][2], w2, hB.x); ffma2(acc[2][3], w2, hB.y);
                    ull w3 = pack2(w.w, w.w);
                    ffma2(acc[3][0], w3, hA.x); ffma2(acc[3][1], w3, hA.y);
                    ffma2(acc[3][2], w3, hB.x); ffma2(acc[3][3], w3, hB.y);
                }
            }
            if (l == 0) {
                const float4* wi = (const float4*)g_decWih0P4 + c;
                const float* dp = din + bh * 8;
#pragma unroll 4
                for (int k = 0; k < IN_DIM; ++k) {
                    float4 w = wi[k * 128];
                    ulonglong2 dA = *(const ulonglong2*)(dp + k * TB);
                    ulonglong2 dB = *(const ulonglong2*)(dp + k * TB + 4);
                    ull w0 = pack2(w.x, w.x);
                    ffma2(acc[0][0], w0, dA.x); ffma2(acc[0][1], w0, dA.y);
                    ffma2(acc[0][2], w0, dB.x); ffma2(acc[0][3], w0, dB.y);
                    ull w1 = pack2(w.y, w.y);
                    ffma2(acc[1][0], w1, dA.x); ffma2(acc[1][1], w1, dA.y);
                    ffma2(acc[1][2], w1, dB.x); ffma2(acc[1][3], w1, dB.y);
                    ull w2 = pack2(w.z, w.z);
                    ffma2(acc[2][0], w2, dA.x); ffma2(acc[2][1], w2, dA.y);
                    ffma2(acc[2][2], w2, dB.x); ffma2(acc[2][3], w2, dB.y);
                    ull w3 = pack2(w.w, w.w);
                    ffma2(acc[3][0], w3, dA.x); ffma2(acc[3][1], w3, dA.y);
                    ffma2(acc[3][2], w3, dB.x); ffma2(acc[3][3], w3, dB.y);
                }
            } else {
                const float4* wi = (const float4*)g_decWihRP4 + (long)(l - 1) * H * H + c;
                const float* hp2 = &h_s[((l - 1) * 2 + cur) * H * TB + bh * 8];
#pragma unroll 8
                for (int k = 0; k < H; ++k) {
                    float4 w = wi[k * 128];
                    ulonglong2 hA = *(const ulonglong2*)(hp2 + k * TB);
                    ulonglong2 hB = *(const ulonglong2*)(hp2 + k * TB + 4);
                    ull w0 = pack2(w.x, w.x);
                    ffma2(acc[0][0], w0, hA.x); ffma2(acc[0][1], w0, hA.y);
                    ffma2(acc[0][2], w0, hB.x); ffma2(acc[0][3], w0, hB.y);
                    ull w1 = pack2(w.y, w.y);
                    ffma2(acc[1][0], w1, hA.x); ffma2(acc[1][1], w1, hA.y);
                    ffma2(acc[1][2], w1, hB.x); ffma2(acc[1][3], w1, hB.y);
                    ull w2 = pack2(w.z, w.z);
                    ffma2(acc[2][0], w2, hA.x); ffma2(acc[2][1], w2, hA.y);
                    ffma2(acc[2][2], w2, hB.x); ffma2(acc[2][3], w2, hB.y);
                    ull w3 = pack2(w.w, w.w);
                    ffma2(acc[3][0], w3, hA.x); ffma2(acc[3][1], w3, hA.y);
                    ffma2(acc[3][2], w3, hB.x); ffma2(acc[3][3], w3, hB.y);
                }
            }
            float4 bb = bias[l];
            float hv[8];
#pragma unroll
            for (int p = 0; p < 4; ++p) {
                float i0, i1, f0, f1, g0, g1, o0, o1;
                unpack2(acc[0][p], i0, i1);
                unpack2(acc[1][p], f0, f1);
                unpack2(acc[2][p], g0, g1);
                unpack2(acc[3][p], o0, o1);
                int b = 2 * p;
                {
                    float gi = i0 + bb.x, gf = f0 + bb.y, gg = g0 + bb.z, go = o0 + bb.w;
                    float cn = sigf(gf) * c_reg[l * 8 + b] + sigf(gi) * tanha(gg);
                    c_reg[l * 8 + b] = cn;
                    hv[b] = sigf(go) * tanha(cn);
                }
                b = 2 * p + 1;
                {
                    float gi = i1 + bb.x, gf = f1 + bb.y, gg = g1 + bb.z, go = o1 + bb.w;
                    float cn = sigf(gf) * c_reg[l * 8 + b] + sigf(gi) * tanha(gg);
                    c_reg[l * 8 + b] = cn;
                    hv[b] = sigf(go) * tanha(cn);
                }
            }
            float* hw = &h_s[((l * 2 + cur) * H + c) * TB + bh * 8];
            *(float4*)hw       = make_float4(hv[0], hv[1], hv[2], hv[3]);
            *(float4*)(hw + 4) = make_float4(hv[4], hv[5], hv[6], hv[7]);
            __syncthreads();
        }
        const float* h3 = &h_s[(3 * 2 + cur) * H * TB];
        for (int idx = tid; idx < TB * IN_DIM; idx += 256) {
            int b = idx / IN_DIM, j = idx - b * IN_DIM;
            float s = fcb[j];
#pragma unroll 8
            for (int k = 0; k < H; ++k)
                s += h3[k * TB + b] * fcw[k * IN_DIM + j];
            out[((long)(b0 + b) * TDEC + t) * IN_DIM + j] = s;
            din[j * TB + b] = s;
        }
        __syncthreads();
    }
}

// ---------------------------------------------------------------------------
// Host launcher
// ---------------------------------------------------------------------------
extern "C" void kernel_launch(void* const* d_in, const int* in_sizes, int n_in,
                              void* d_out, int out_size) {
    const float* x        = (const float*)d_in[0];
    const float* enc_Wih0 = (const float*)d_in[2];
    const float* enc_WihR = (const float*)d_in[3];
    const float* enc_Whh  = (const float*)d_in[4];
    const float* enc_b    = (const float*)d_in[5];
    const float* dec_Wih0 = (const float*)d_in[6];
    const float* dec_WihR = (const float*)d_in[7];
    const float* dec_Whh  = (const float*)d_in[8];
    const float* dec_b    = (const float*)d_in[9];
    const float* fc_W     = (const float*)d_in[10];
    const float* fc_b     = (const float*)d_in[11];
    float* out = (float*)d_out;

    float *encBP, *decBP;
    float *encWhhP4, *decWhhP4, *decWihRP4, *decWih0P4, *fcT;
    float *Xg, *hSt, *cSt;
    bf16 *W0H, *W0L, *WRH, *WRL, *ysH, *ysL, *x0H, *x0L;
    cudaGetSymbolAddress((void**)&encBP,     g_encBP);
    cudaGetSymbolAddress((void**)&decBP,     g_decBP);
    cudaGetSymbolAddress((void**)&encWhhP4,  g_encWhhP4);
    cudaGetSymbolAddress((void**)&decWhhP4,  g_decWhhP4);
    cudaGetSymbolAddress((void**)&decWihRP4, g_decWihRP4);
    cudaGetSymbolAddress((void**)&decWih0P4, g_decWih0P4);
    cudaGetSymbolAddress((void**)&fcT,       g_fcT);
    cudaGetSymbolAddress((void**)&Xg,        g_Xg);
    cudaGetSymbolAddress((void**)&hSt,       g_h);
    cudaGetSymbolAddress((void**)&cSt,       g_c);
    cudaGetSymbolAddress((void**)&W0H,       g_W0H);
    cudaGetSymbolAddress((void**)&W0L,       g_W0L);
    cudaGetSymbolAddress((void**)&WRH,       g_WRH);
    cudaGetSymbolAddress((void**)&WRL,       g_WRL);
    cudaGetSymbolAddress((void**)&ysH,       g_ysH);
    cudaGetSymbolAddress((void**)&ysL,       g_ysL);
    cudaGetSymbolAddress((void**)&x0H,       g_x0H);
    cudaGetSymbolAddress((void**)&x0L,       g_x0L);

    cudaFuncSetAttribute(k_decoder, cudaFuncAttributeMaxDynamicSharedMemorySize,
                         DEC_SMEM_BYTES);
    // GEMM dynamic smem: 2*BSP + 4*ASP + 1024
    const int DYN48  = 2 * (256 * 112) + 4 * (64 * 112) + 1024;   // 87,040
    const int DYN128 = 2 * (256 * 272) + 4 * (64 * 272) + 1024;   // 210,944
    cudaFuncSetAttribute(k_mmagemm<48>,
                         cudaFuncAttributeMaxDynamicSharedMemorySize, DYN48);
    cudaFuncSetAttribute(k_mmagemm<128>,
                         cudaFuncAttributeMaxDynamicSharedMemorySize, DYN128);

    // prep
    k_misc<<<(4096 + H * IN_DIM + 255) / 256, 256>>>(enc_b, dec_b, fc_W,
                                                     encBP, decBP, fcT);
    {
        GPJobs jg; jg.n = 12;
        for (int l = 0; l < NL; ++l)
            jg.j[l] = { enc_Whh + (long)l * H4 * H, encWhhP4 + (long)l * H * H * 4, H };
        for (int l = 0; l < NL; ++l)
            jg.j[4 + l] = { dec_Whh + (long)l * H4 * H, decWhhP4 + (long)l * H * H * 4, H };
        for (int r = 0; r < 3; ++r)
            jg.j[8 + r] = { dec_WihR + (long)r * H4 * H, decWihRP4 + (long)r * H * H * 4, H };
        jg.j[11] = { dec_Wih0, decWih0P4, IN_DIM };
        dim3 g(128, 12);
        k_pack4g<<<g, 128>>>(jg);
    }
    {
        dim3 g(256, 4);
        k_wconv<<<g, 256>>>(enc_Wih0, enc_WihR, W0H, W0L, WRH, WRL);
    }
    k_xconv<<<2048, 256>>>(x, x0H, x0L);

    dim3 ggrid(GBX, 2);

    // encoder layer 0
    k_mmagemm<48><<<ggrid, 256, DYN48>>>(x0H, x0L, W0H, W0L, encBP, Xg);
    k_lstm_seq<true><<<BATCH / TB, 256>>>((const float4*)encWhhP4, ysH, ysL, hSt, cSt);
    // encoder layers 1..3
    for (int l = 1; l < NL; ++l) {
        k_mmagemm<128><<<ggrid, 256, DYN128>>>(
            ysH, ysL, WRH + (long)(l - 1) * 512 * 128, WRL + (long)(l - 1) * 512 * 128,
            encBP + (long)l * H4, Xg);
        if (l < NL - 1)
            k_lstm_seq<true><<<BATCH / TB, 256>>>(
                (const float4*)(encWhhP4 + (long)l * H * H * 4), ysH, ysL,
                hSt + (long)l * BATCH * H, cSt + (long)l * BATCH * H);
        else
            k_lstm_seq<false><<<BATCH / TB, 256>>>(
                (const float4*)(encWhhP4 + (long)l * H * H * 4), nullptr, nullptr,
                hSt + (long)l * BATCH * H, cSt + (long)l * BATCH * H);
    }
    // fused decoder
    k_decoder<<<BATCH / TB, 256, DEC_SMEM_BYTES>>>(x, fc_b, out);
}